// round 1
// baseline (speedup 1.0000x reference)
#include <cuda_runtime.h>
#include <cuda_bf16.h>
#include <math.h>

// ---------------------------------------------------------------------------
// SmallTransformerBlock: B=4, T=2048, D=1024, FF=4096, full-D attention,
// scale = sqrt(D / n_heads) = sqrt(128).
//
// Round 1: correct fp32 baseline. 128x128x8 register-blocked SGEMM (8x8 per
// thread, 256 threads), fused bias/ReLU/residual epilogues, batched attention
// GEMMs via grid.z, row softmax with fused 1/scale, block-per-row LayerNorm.
// ---------------------------------------------------------------------------

#define D_MODEL 1024
#define FF_DIM  4096
#define BATCH   4
#define SEQ     2048
#define M_TOT   (BATCH * SEQ)          // 8192

// Scratch (device globals; allocation inside kernel_launch is forbidden)
__device__ float g_q  [M_TOT * D_MODEL];
__device__ float g_k  [M_TOT * D_MODEL];
__device__ float g_v  [M_TOT * D_MODEL];
__device__ float g_s  [BATCH * SEQ * SEQ];
__device__ float g_ctx[M_TOT * D_MODEL];
__device__ float g_x1 [M_TOT * D_MODEL];
__device__ float g_y1 [M_TOT * D_MODEL];
__device__ float g_h  [M_TOT * FF_DIM];
__device__ float g_x2 [M_TOT * D_MODEL];

// ---------------------------------------------------------------------------
// SGEMM: C = A @ B (+bias)(ReLU?)(+Res?), tiles 128x128, BK=8, 256 threads.
// TRANSB=false: B is [K,N] row-major. TRANSB=true: B is [N,K] row-major.
// All dims are multiples of 128 in this problem -> no bounds checks.
// ---------------------------------------------------------------------------
template<bool TRANSB, bool RELU, bool HASRES>
__global__ __launch_bounds__(256, 2) void sgemm_kernel(
    const float* __restrict__ A, const float* __restrict__ B,
    const float* __restrict__ bias, const float* __restrict__ Res,
    float* __restrict__ C, int M, int N, int K,
    long long sA, long long sB, long long sC)
{
    __shared__ float As[8][128];
    __shared__ float Bs[8][128];

    A += (long long)blockIdx.z * sA;
    B += (long long)blockIdx.z * sB;
    C += (long long)blockIdx.z * sC;
    const float* ResP = HASRES ? Res : nullptr;

    const int tid = threadIdx.x;
    const int bm = blockIdx.y * 128;
    const int bn = blockIdx.x * 128;

    // A (and NT-B) tile loads: 128 rows x 8 k, one float4 per thread
    const int lr = tid >> 1;          // 0..127
    const int lc = (tid & 1) * 4;     // 0 or 4
    // NN-B tile loads: 8 k-rows x 128 n, one float4 per thread
    const int br = tid >> 5;          // 0..7
    const int bc = (tid & 31) * 4;    // 0..124

    const int tx = tid & 15;          // n micro-tile
    const int ty = tid >> 4;          // m micro-tile

    float acc[8][8];
    #pragma unroll
    for (int i = 0; i < 8; i++)
        #pragma unroll
        for (int j = 0; j < 8; j++) acc[i][j] = 0.0f;

    const float* Aptr = A + (long long)(bm + lr) * K + lc;

    for (int k0 = 0; k0 < K; k0 += 8) {
        float4 av = *(const float4*)(Aptr + k0);
        As[lc + 0][lr] = av.x;
        As[lc + 1][lr] = av.y;
        As[lc + 2][lr] = av.z;
        As[lc + 3][lr] = av.w;
        if (TRANSB) {
            float4 bv = *(const float4*)(B + (long long)(bn + lr) * K + k0 + lc);
            Bs[lc + 0][lr] = bv.x;
            Bs[lc + 1][lr] = bv.y;
            Bs[lc + 2][lr] = bv.z;
            Bs[lc + 3][lr] = bv.w;
        } else {
            float4 bv = *(const float4*)(B + (long long)(k0 + br) * N + bn + bc);
            *(float4*)&Bs[br][bc] = bv;
        }
        __syncthreads();

        #pragma unroll
        for (int kk = 0; kk < 8; kk++) {
            float ra[8], rb[8];
            *(float4*)&ra[0] = *(const float4*)&As[kk][ty * 8];
            *(float4*)&ra[4] = *(const float4*)&As[kk][ty * 8 + 4];
            *(float4*)&rb[0] = *(const float4*)&Bs[kk][tx * 8];
            *(float4*)&rb[4] = *(const float4*)&Bs[kk][tx * 8 + 4];
            #pragma unroll
            for (int i = 0; i < 8; i++)
                #pragma unroll
                for (int j = 0; j < 8; j++)
                    acc[i][j] = fmaf(ra[i], rb[j], acc[i][j]);
        }
        __syncthreads();
    }

    // Epilogue: bias -> (relu) -> (+residual) -> store
    float bcol[8];
    #pragma unroll
    for (int j = 0; j < 8; j++)
        bcol[j] = bias ? bias[bn + tx * 8 + j] : 0.0f;

    #pragma unroll
    for (int i = 0; i < 8; i++) {
        long long off = (long long)(bm + ty * 8 + i) * N + bn + tx * 8;
        float out[8];
        #pragma unroll
        for (int j = 0; j < 8; j++) {
            float v2 = acc[i][j] + bcol[j];
            if (RELU) v2 = fmaxf(v2, 0.0f);
            out[j] = v2;
        }
        if (HASRES) {
            float4 r0 = *(const float4*)(ResP + off);
            float4 r1 = *(const float4*)(ResP + off + 4);
            out[0] += r0.x; out[1] += r0.y; out[2] += r0.z; out[3] += r0.w;
            out[4] += r1.x; out[5] += r1.y; out[6] += r1.z; out[7] += r1.w;
        }
        *(float4*)(C + off)     = make_float4(out[0], out[1], out[2], out[3]);
        *(float4*)(C + off + 4) = make_float4(out[4], out[5], out[6], out[7]);
    }
}

// ---------------------------------------------------------------------------
// Block reductions (256 threads)
// ---------------------------------------------------------------------------
__device__ __forceinline__ float block_sum(float v) {
    __shared__ float sh[8];
    int lane = threadIdx.x & 31, w = threadIdx.x >> 5;
    #pragma unroll
    for (int o = 16; o > 0; o >>= 1) v += __shfl_xor_sync(0xffffffffu, v, o);
    if (lane == 0) sh[w] = v;
    __syncthreads();
    if (w == 0) {
        float t = (lane < 8) ? sh[lane] : 0.0f;
        #pragma unroll
        for (int o = 4; o > 0; o >>= 1) t += __shfl_xor_sync(0xffffffffu, t, o);
        if (lane == 0) sh[0] = t;
    }
    __syncthreads();
    float r = sh[0];
    __syncthreads();
    return r;
}

__device__ __forceinline__ float block_max(float v) {
    __shared__ float sh[8];
    int lane = threadIdx.x & 31, w = threadIdx.x >> 5;
    #pragma unroll
    for (int o = 16; o > 0; o >>= 1) v = fmaxf(v, __shfl_xor_sync(0xffffffffu, v, o));
    if (lane == 0) sh[w] = v;
    __syncthreads();
    if (w == 0) {
        float t = (lane < 8) ? sh[lane] : -3.4e38f;
        #pragma unroll
        for (int o = 4; o > 0; o >>= 1) t = fmaxf(t, __shfl_xor_sync(0xffffffffu, t, o));
        if (lane == 0) sh[0] = t;
    }
    __syncthreads();
    float r = sh[0];
    __syncthreads();
    return r;
}

// ---------------------------------------------------------------------------
// Softmax over rows of length SEQ=2048 (in-place), 1/scale fused. 256 threads,
// 8 values per thread.
// ---------------------------------------------------------------------------
__global__ __launch_bounds__(256) void softmax_kernel(float* __restrict__ S) {
    const float inv_scale = 0.0883883476483184f;  // 1/sqrt(128)
    float* row = S + (long long)blockIdx.x * SEQ;
    int tid = threadIdx.x;

    float4 a = ((const float4*)row)[tid];
    float4 b = ((const float4*)row)[tid + 256];
    a.x *= inv_scale; a.y *= inv_scale; a.z *= inv_scale; a.w *= inv_scale;
    b.x *= inv_scale; b.y *= inv_scale; b.z *= inv_scale; b.w *= inv_scale;

    float m = fmaxf(fmaxf(fmaxf(a.x, a.y), fmaxf(a.z, a.w)),
                    fmaxf(fmaxf(b.x, b.y), fmaxf(b.z, b.w)));
    m = block_max(m);

    a.x = expf(a.x - m); a.y = expf(a.y - m); a.z = expf(a.z - m); a.w = expf(a.w - m);
    b.x = expf(b.x - m); b.y = expf(b.y - m); b.z = expf(b.z - m); b.w = expf(b.w - m);

    float s = a.x + a.y + a.z + a.w + b.x + b.y + b.z + b.w;
    s = block_sum(s);
    float inv = 1.0f / s;

    a.x *= inv; a.y *= inv; a.z *= inv; a.w *= inv;
    b.x *= inv; b.y *= inv; b.z *= inv; b.w *= inv;
    ((float4*)row)[tid]       = a;
    ((float4*)row)[tid + 256] = b;
}

// ---------------------------------------------------------------------------
// LayerNorm over D=1024. One block per row, 256 threads, 1 float4 each.
// ---------------------------------------------------------------------------
__global__ __launch_bounds__(256) void layernorm_kernel(
    const float* __restrict__ X, const float* __restrict__ g,
    const float* __restrict__ b, float* __restrict__ Y)
{
    const float* x = X + (long long)blockIdx.x * D_MODEL;
    float*       y = Y + (long long)blockIdx.x * D_MODEL;
    int tid = threadIdx.x;

    float4 v = ((const float4*)x)[tid];
    float s = v.x + v.y + v.z + v.w;
    s = block_sum(s);
    float mean = s * (1.0f / D_MODEL);

    float dx = v.x - mean, dy = v.y - mean, dz = v.z - mean, dw = v.w - mean;
    float ss = dx * dx + dy * dy + dz * dz + dw * dw;
    ss = block_sum(ss);
    float var = ss * (1.0f / D_MODEL);
    float rstd = rsqrtf(var + 1e-5f);

    float4 gg = ((const float4*)g)[tid];
    float4 bb = ((const float4*)b)[tid];
    float4 o;
    o.x = dx * rstd * gg.x + bb.x;
    o.y = dy * rstd * gg.y + bb.y;
    o.z = dz * rstd * gg.z + bb.z;
    o.w = dw * rstd * gg.w + bb.w;
    ((float4*)y)[tid] = o;
}

// ---------------------------------------------------------------------------
// Launch
// ---------------------------------------------------------------------------
extern "C" void kernel_launch(void* const* d_in, const int* in_sizes, int n_in,
                              void* d_out, int out_size)
{
    const float* x     = (const float*)d_in[0];
    const float* wq    = (const float*)d_in[1];
    const float* bq    = (const float*)d_in[2];
    const float* wk    = (const float*)d_in[3];
    const float* bk    = (const float*)d_in[4];
    const float* wv    = (const float*)d_in[5];
    const float* bv    = (const float*)d_in[6];
    const float* wo    = (const float*)d_in[7];
    const float* bo    = (const float*)d_in[8];
    const float* w1    = (const float*)d_in[9];
    const float* b1    = (const float*)d_in[10];
    const float* w2    = (const float*)d_in[11];
    const float* b2    = (const float*)d_in[12];
    const float* g1    = (const float*)d_in[13];
    const float* beta1 = (const float*)d_in[14];
    const float* g2    = (const float*)d_in[15];
    const float* beta2 = (const float*)d_in[16];
    float* out = (float*)d_out;

    float *q, *k, *v, *s, *ctx, *x1, *y1, *h, *x2;
    cudaGetSymbolAddress((void**)&q,   g_q);
    cudaGetSymbolAddress((void**)&k,   g_k);
    cudaGetSymbolAddress((void**)&v,   g_v);
    cudaGetSymbolAddress((void**)&s,   g_s);
    cudaGetSymbolAddress((void**)&ctx, g_ctx);
    cudaGetSymbolAddress((void**)&x1,  g_x1);
    cudaGetSymbolAddress((void**)&y1,  g_y1);
    cudaGetSymbolAddress((void**)&h,   g_h);
    cudaGetSymbolAddress((void**)&x2,  g_x2);

    dim3 blk(256);

    // Q, K, V projections: [8192,1024] @ [1024,1024]
    {
        dim3 grid(D_MODEL / 128, M_TOT / 128, 1);
        sgemm_kernel<false, false, false><<<grid, blk>>>(x, wq, bq, nullptr, q,
            M_TOT, D_MODEL, D_MODEL, 0, 0, 0);
        sgemm_kernel<false, false, false><<<grid, blk>>>(x, wk, bk, nullptr, k,
            M_TOT, D_MODEL, D_MODEL, 0, 0, 0);
        sgemm_kernel<false, false, false><<<grid, blk>>>(x, wv, bv, nullptr, v,
            M_TOT, D_MODEL, D_MODEL, 0, 0, 0);
    }

    // scores[b] = Q_b @ K_b^T : [2048,1024] x [2048,1024]^T -> [2048,2048]
    {
        dim3 grid(SEQ / 128, SEQ / 128, BATCH);
        sgemm_kernel<true, false, false><<<grid, blk>>>(q, k, nullptr, nullptr, s,
            SEQ, SEQ, D_MODEL,
            (long long)SEQ * D_MODEL, (long long)SEQ * D_MODEL, (long long)SEQ * SEQ);
    }

    // softmax rows (scale fused)
    softmax_kernel<<<BATCH * SEQ, blk>>>(s);

    // ctx[b] = attn_b @ V_b : [2048,2048] x [2048,1024]
    {
        dim3 grid(D_MODEL / 128, SEQ / 128, BATCH);
        sgemm_kernel<false, false, false><<<grid, blk>>>(s, v, nullptr, nullptr, ctx,
            SEQ, D_MODEL, SEQ,
            (long long)SEQ * SEQ, (long long)SEQ * D_MODEL, (long long)SEQ * D_MODEL);
    }

    // x1 = x + ctx @ wo + bo
    {
        dim3 grid(D_MODEL / 128, M_TOT / 128, 1);
        sgemm_kernel<false, false, true><<<grid, blk>>>(ctx, wo, bo, x, x1,
            M_TOT, D_MODEL, D_MODEL, 0, 0, 0);
    }

    // y1 = LN1(x1)
    layernorm_kernel<<<M_TOT, blk>>>(x1, g1, beta1, y1);

    // h = relu(y1 @ w1 + b1) : [8192,1024] x [1024,4096]
    {
        dim3 grid(FF_DIM / 128, M_TOT / 128, 1);
        sgemm_kernel<false, true, false><<<grid, blk>>>(y1, w1, b1, nullptr, h,
            M_TOT, FF_DIM, D_MODEL, 0, 0, 0);
    }

    // x2 = y1 + h @ w2 + b2 : [8192,4096] x [4096,1024]
    {
        dim3 grid(D_MODEL / 128, M_TOT / 128, 1);
        sgemm_kernel<false, false, true><<<grid, blk>>>(h, w2, b2, y1, x2,
            M_TOT, D_MODEL, FF_DIM, 0, 0, 0);
    }

    // out = LN2(x2)
    layernorm_kernel<<<M_TOT, blk>>>(x2, g2, beta2, out);
}

// round 3
// speedup vs baseline: 2.1136x; 2.1136x over previous
#include <cuda_runtime.h>
#include <cuda_bf16.h>
#include <math.h>
#include <stdint.h>

// ---------------------------------------------------------------------------
// SmallTransformerBlock via mma.sync bf16x3 split GEMMs (sm_103 baseline PTX;
// tcgen05 is unavailable because the harness emits compute_103 PTX).
// B=4, T=2048, D=1024, FF=4096. All GEMMs NT: C = A[M,K] @ B[N,K]^T.
// fp32 operand x = hi + lo (bf16); accumulate Ah*Bh + Ah*Bl + Al*Bh in fp32.
// ---------------------------------------------------------------------------

#define D_MODEL 1024
#define FF_DIM  4096
#define BATCH   4
#define SEQ     2048
#define M_TOT   (BATCH * SEQ)          // 8192

#define BM 128
#define BN 128
#define BK 32
#define STAGES 3
// SMEM row stride 80B (64B data + 16B pad -> conflict-free ldmatrix)
#define ROWB 80
#define OFF_AH 0
#define OFF_AL (128 * ROWB)
#define OFF_BH (2 * 128 * ROWB)
#define OFF_BL (3 * 128 * ROWB)
#define STAGE_BYTES (4 * 128 * ROWB)          // 40960
#define SMEM_TOTAL  (STAGES * STAGE_BYTES)    // 122880

typedef __nv_bfloat16 bf16;

// -------------------------- scratch (device globals) -----------------------
__device__ bf16  g_x_hi [M_TOT * D_MODEL];
__device__ bf16  g_x_lo [M_TOT * D_MODEL];
__device__ bf16  g_wqT_hi[D_MODEL * D_MODEL];
__device__ bf16  g_wqT_lo[D_MODEL * D_MODEL];
__device__ bf16  g_wkT_hi[D_MODEL * D_MODEL];
__device__ bf16  g_wkT_lo[D_MODEL * D_MODEL];
__device__ bf16  g_wvT_hi[D_MODEL * D_MODEL];
__device__ bf16  g_wvT_lo[D_MODEL * D_MODEL];
__device__ bf16  g_woT_hi[D_MODEL * D_MODEL];
__device__ bf16  g_woT_lo[D_MODEL * D_MODEL];
__device__ bf16  g_w1T_hi[FF_DIM * D_MODEL];
__device__ bf16  g_w1T_lo[FF_DIM * D_MODEL];
__device__ bf16  g_w2T_hi[D_MODEL * FF_DIM];
__device__ bf16  g_w2T_lo[D_MODEL * FF_DIM];
__device__ bf16  g_q_hi [M_TOT * D_MODEL];
__device__ bf16  g_q_lo [M_TOT * D_MODEL];
__device__ bf16  g_k_hi [M_TOT * D_MODEL];
__device__ bf16  g_k_lo [M_TOT * D_MODEL];
__device__ float g_v    [M_TOT * D_MODEL];
__device__ bf16  g_vT_hi[M_TOT * D_MODEL];     // [B][D,T]
__device__ bf16  g_vT_lo[M_TOT * D_MODEL];
__device__ float g_s    [BATCH * SEQ * SEQ];
__device__ bf16  g_p_hi [BATCH * SEQ * SEQ];
__device__ bf16  g_p_lo [BATCH * SEQ * SEQ];
__device__ bf16  g_ctx_hi[M_TOT * D_MODEL];
__device__ bf16  g_ctx_lo[M_TOT * D_MODEL];
__device__ float g_x1   [M_TOT * D_MODEL];
__device__ float g_y1   [M_TOT * D_MODEL];
__device__ bf16  g_y1_hi[M_TOT * D_MODEL];
__device__ bf16  g_y1_lo[M_TOT * D_MODEL];
__device__ bf16  g_h_hi [M_TOT * FF_DIM];
__device__ bf16  g_h_lo [M_TOT * FF_DIM];
__device__ float g_x2   [M_TOT * D_MODEL];

// ------------------------------- PTX helpers -------------------------------
__device__ __forceinline__ uint32_t smem_u32(const void* p) {
    uint32_t a;
    asm("{ .reg .u64 t; cvta.to.shared.u64 t, %1; cvt.u32.u64 %0, t; }"
        : "=r"(a) : "l"(p));
    return a;
}
__device__ __forceinline__ void cp16(uint32_t dst, const void* src) {
    asm volatile("cp.async.cg.shared.global [%0], [%1], 16;\n" :: "r"(dst), "l"(src));
}
__device__ __forceinline__ void cp_commit() {
    asm volatile("cp.async.commit_group;\n" ::: "memory");
}
template<int N> __device__ __forceinline__ void cp_wait() {
    asm volatile("cp.async.wait_group %0;\n" :: "n"(N) : "memory");
}
__device__ __forceinline__ void ldsm4(uint32_t& r0, uint32_t& r1, uint32_t& r2,
                                      uint32_t& r3, uint32_t addr) {
    asm volatile("ldmatrix.sync.aligned.m8n8.x4.shared.b16 {%0,%1,%2,%3}, [%4];\n"
                 : "=r"(r0), "=r"(r1), "=r"(r2), "=r"(r3) : "r"(addr));
}
__device__ __forceinline__ void mma16816(float* d, const uint32_t* a, const uint32_t* b) {
    asm volatile(
        "mma.sync.aligned.m16n8k16.row.col.f32.bf16.bf16.f32 "
        "{%0,%1,%2,%3}, {%4,%5,%6,%7}, {%8,%9}, {%0,%1,%2,%3};\n"
        : "+f"(d[0]), "+f"(d[1]), "+f"(d[2]), "+f"(d[3])
        : "r"(a[0]), "r"(a[1]), "r"(a[2]), "r"(a[3]), "r"(b[0]), "r"(b[1]));
}
__device__ __forceinline__ void split1(float v, bf16& h, bf16& l) {
    h = __float2bfloat16(v);
    l = __float2bfloat16(v - __bfloat162float(h));
}
__device__ __forceinline__ uint32_t pack2(bf16 a, bf16 b) {
    return ((uint32_t)__bfloat16_as_ushort(b) << 16) | __bfloat16_as_ushort(a);
}

// ---------------------------------------------------------------------------
// GEMM NT bf16x3: C[M,N] = (Ah+Al) @ (Bh+Bl)^T (+bias)(relu)(+res)
// 128x128x32 tile, 8 warps (warp tile 32x64), 3-stage cp.async pipeline.
// ---------------------------------------------------------------------------
template<bool F32OUT, bool SPLITOUT, bool RELU, bool HASRES>
__global__ __launch_bounds__(256, 1) void gemm_nt(
    const bf16* __restrict__ Ahi, const bf16* __restrict__ Alo,
    const bf16* __restrict__ Bhi, const bf16* __restrict__ Blo,
    const float* __restrict__ bias, const float* __restrict__ Res,
    float* __restrict__ Cf, bf16* __restrict__ Chi, bf16* __restrict__ Clo,
    int M, int N, int K, long long aS, long long bS, long long cS)
{
    extern __shared__ char smraw[];
    const uint32_t smb = smem_u32(smraw);
    const int tid  = threadIdx.x;
    const int wid  = tid >> 5;
    const int lane = tid & 31;
    const int wm = wid & 3;            // 0..3 -> m offset wm*32
    const int wn = wid >> 2;           // 0..1 -> n offset wn*64
    const int quad = lane >> 3, lrow = lane & 7;
    const int bz = blockIdx.z;
    const int bm = blockIdx.y * BM;
    const int bn = blockIdx.x * BN;

    const bf16* Ah = Ahi + (long long)bz * aS;
    const bf16* Al = Alo + (long long)bz * aS;
    const bf16* Bh = Bhi + (long long)bz * bS;
    const bf16* Bl = Blo + (long long)bz * bS;

    float acc[2][8][4];
    #pragma unroll
    for (int i = 0; i < 2; i++)
        #pragma unroll
        for (int j = 0; j < 8; j++)
            #pragma unroll
            for (int c = 0; c < 4; c++) acc[i][j][c] = 0.0f;

    const int T = K / BK;

    auto load_stage = [&](int kt, int s) {
        const uint32_t st = smb + s * STAGE_BYTES;
        const int k0 = kt * BK;
        #pragma unroll
        for (int i = 0; i < 2; i++) {
            int id  = tid + i * 256;
            int row = id >> 2, c = id & 3;
            uint32_t off = (uint32_t)(row * ROWB + c * 16);
            long long ga = (long long)(bm + row) * K + k0 + c * 8;
            long long gb = (long long)(bn + row) * K + k0 + c * 8;
            cp16(st + OFF_AH + off, Ah + ga);
            cp16(st + OFF_AL + off, Al + ga);
            cp16(st + OFF_BH + off, Bh + gb);
            cp16(st + OFF_BL + off, Bl + gb);
        }
    };

    auto compute_stage = [&](int s) {
        const uint32_t st = smb + s * STAGE_BYTES;
        #pragma unroll
        for (int ks = 0; ks < 2; ks++) {
            const uint32_t cb = (uint32_t)(ks * 32 + (quad >> 1) * 16);
            uint32_t ah[2][4], al[2][4], bhf[8][2], blf[8][2];
            #pragma unroll
            for (int fm = 0; fm < 2; fm++) {
                uint32_t r = (uint32_t)(wm * 32 + fm * 16 + (quad & 1) * 8 + lrow);
                uint32_t a = st + r * ROWB + cb;
                ldsm4(ah[fm][0], ah[fm][1], ah[fm][2], ah[fm][3], a + OFF_AH);
                ldsm4(al[fm][0], al[fm][1], al[fm][2], al[fm][3], a + OFF_AL);
            }
            #pragma unroll
            for (int f2 = 0; f2 < 4; f2++) {
                uint32_t r = (uint32_t)(wn * 64 + f2 * 16 + (quad & 1) * 8 + lrow);
                uint32_t a = st + r * ROWB + cb;
                uint32_t t0, t1, t2, t3;
                ldsm4(t0, t1, t2, t3, a + OFF_BH);
                bhf[2*f2][0] = t0; bhf[2*f2][1] = t2;
                bhf[2*f2+1][0] = t1; bhf[2*f2+1][1] = t3;
                ldsm4(t0, t1, t2, t3, a + OFF_BL);
                blf[2*f2][0] = t0; blf[2*f2][1] = t2;
                blf[2*f2+1][0] = t1; blf[2*f2+1][1] = t3;
            }
            #pragma unroll
            for (int fm = 0; fm < 2; fm++)
                #pragma unroll
                for (int fn = 0; fn < 8; fn++) {
                    mma16816(acc[fm][fn], ah[fm], bhf[fn]);
                    mma16816(acc[fm][fn], ah[fm], blf[fn]);
                    mma16816(acc[fm][fn], al[fm], bhf[fn]);
                }
        }
    };

    load_stage(0, 0); cp_commit();
    load_stage(1, 1); cp_commit();

    for (int t = 0; t < T; t++) {
        if (t < T - 1) cp_wait<1>(); else cp_wait<0>();
        __syncthreads();
        if (t + 2 < T) { load_stage(t + 2, (t + 2) % STAGES); cp_commit(); }
        compute_stage(t % STAGES);
    }

    // ---------------- epilogue ----------------
    const int groupID = lane >> 2, tIdx = lane & 3;
    #pragma unroll
    for (int fm = 0; fm < 2; fm++) {
        #pragma unroll
        for (int half = 0; half < 2; half++) {
            int row = bm + wm * 32 + fm * 16 + half * 8 + groupID;
            long long rbase = (long long)bz * cS + (long long)row * N;
            #pragma unroll
            for (int fn = 0; fn < 8; fn++) {
                int col = bn + wn * 64 + fn * 8 + tIdx * 2;
                float v0 = acc[fm][fn][half * 2 + 0];
                float v1 = acc[fm][fn][half * 2 + 1];
                if (bias) { v0 += __ldg(bias + col); v1 += __ldg(bias + col + 1); }
                if (RELU) { v0 = fmaxf(v0, 0.0f); v1 = fmaxf(v1, 0.0f); }
                if (HASRES) {
                    float2 rv = *(const float2*)(Res + rbase + col);
                    v0 += rv.x; v1 += rv.y;
                }
                if (F32OUT)
                    *(float2*)(Cf + rbase + col) = make_float2(v0, v1);
                if (SPLITOUT) {
                    bf16 h0, l0, h1, l1;
                    split1(v0, h0, l0); split1(v1, h1, l1);
                    *(uint32_t*)(Chi + rbase + col) = pack2(h0, h1);
                    *(uint32_t*)(Clo + rbase + col) = pack2(l0, l1);
                }
            }
        }
    }
}

// ---------------------------------------------------------------------------
// Elementwise split: fp32 -> (hi, lo) bf16
// ---------------------------------------------------------------------------
__global__ __launch_bounds__(256) void split_kernel(
    const float* __restrict__ src, bf16* __restrict__ hi, bf16* __restrict__ lo, int n4)
{
    int i = blockIdx.x * 256 + threadIdx.x;
    if (i >= n4) return;
    float4 v = ((const float4*)src)[i];
    bf16 h0,l0,h1,l1,h2,l2,h3,l3;
    split1(v.x,h0,l0); split1(v.y,h1,l1); split1(v.z,h2,l2); split1(v.w,h3,l3);
    ((uint2*)hi)[i] = make_uint2(pack2(h0,h1), pack2(h2,h3));
    ((uint2*)lo)[i] = make_uint2(pack2(l0,l1), pack2(l2,l3));
}

// ---------------------------------------------------------------------------
// Transpose-split: src [R,C] fp32 -> dst [C,R] (hi, lo) bf16.
// ---------------------------------------------------------------------------
__global__ __launch_bounds__(256) void transpose_split_kernel(
    const float* __restrict__ src, bf16* __restrict__ hiT, bf16* __restrict__ loT,
    int R, int C, long long sS, long long dS)
{
    __shared__ float tile[32][33];
    const float* S = src + (long long)blockIdx.z * sS;
    int c0 = blockIdx.x * 32, r0 = blockIdx.y * 32;
    int tx = threadIdx.x & 31, ty = threadIdx.x >> 5;   // 32 x 8
    #pragma unroll
    for (int i = 0; i < 32; i += 8)
        tile[ty + i][tx] = S[(long long)(r0 + ty + i) * C + c0 + tx];
    __syncthreads();
    #pragma unroll
    for (int i = 0; i < 32; i += 8) {
        float v = tile[tx][ty + i];
        bf16 h, l; split1(v, h, l);
        long long o = (long long)blockIdx.z * dS + (long long)(c0 + ty + i) * R + r0 + tx;
        hiT[o] = h; loT[o] = l;
    }
}

// ------------------------------- reductions --------------------------------
__device__ __forceinline__ float block_sum(float v) {
    __shared__ float sh[8];
    int lane = threadIdx.x & 31, w = threadIdx.x >> 5;
    #pragma unroll
    for (int o = 16; o > 0; o >>= 1) v += __shfl_xor_sync(0xffffffffu, v, o);
    if (lane == 0) sh[w] = v;
    __syncthreads();
    if (w == 0) {
        float t = (lane < 8) ? sh[lane] : 0.0f;
        #pragma unroll
        for (int o = 4; o > 0; o >>= 1) t += __shfl_xor_sync(0xffffffffu, t, o);
        if (lane == 0) sh[0] = t;
    }
    __syncthreads();
    float r = sh[0];
    __syncthreads();
    return r;
}
__device__ __forceinline__ float block_max(float v) {
    __shared__ float sh[8];
    int lane = threadIdx.x & 31, w = threadIdx.x >> 5;
    #pragma unroll
    for (int o = 16; o > 0; o >>= 1) v = fmaxf(v, __shfl_xor_sync(0xffffffffu, v, o));
    if (lane == 0) sh[w] = v;
    __syncthreads();
    if (w == 0) {
        float t = (lane < 8) ? sh[lane] : -3.4e38f;
        #pragma unroll
        for (int o = 4; o > 0; o >>= 1) t = fmaxf(t, __shfl_xor_sync(0xffffffffu, t, o));
        if (lane == 0) sh[0] = t;
    }
    __syncthreads();
    float r = sh[0];
    __syncthreads();
    return r;
}

// ---------------------------------------------------------------------------
// Softmax over SEQ=2048 with fused 1/scale; outputs pre-split hi/lo bf16.
// ---------------------------------------------------------------------------
__global__ __launch_bounds__(256) void softmax_split_kernel(
    const float* __restrict__ S, bf16* __restrict__ Phi, bf16* __restrict__ Plo)
{
    const float inv_scale = 0.0883883476483184f;  // 1/sqrt(128)
    const float* row = S + (long long)blockIdx.x * SEQ;
    int tid = threadIdx.x;

    float4 a = ((const float4*)row)[tid];
    float4 b = ((const float4*)row)[tid + 256];
    a.x*=inv_scale; a.y*=inv_scale; a.z*=inv_scale; a.w*=inv_scale;
    b.x*=inv_scale; b.y*=inv_scale; b.z*=inv_scale; b.w*=inv_scale;

    float m = fmaxf(fmaxf(fmaxf(a.x,a.y), fmaxf(a.z,a.w)),
                    fmaxf(fmaxf(b.x,b.y), fmaxf(b.z,b.w)));
    m = block_max(m);
    a.x=expf(a.x-m); a.y=expf(a.y-m); a.z=expf(a.z-m); a.w=expf(a.w-m);
    b.x=expf(b.x-m); b.y=expf(b.y-m); b.z=expf(b.z-m); b.w=expf(b.w-m);
    float s = a.x+a.y+a.z+a.w + b.x+b.y+b.z+b.w;
    s = block_sum(s);
    float inv = 1.0f / s;
    a.x*=inv; a.y*=inv; a.z*=inv; a.w*=inv;
    b.x*=inv; b.y*=inv; b.z*=inv; b.w*=inv;

    long long base = (long long)blockIdx.x * SEQ;
    bf16 h0,l0,h1,l1,h2,l2,h3,l3;
    split1(a.x,h0,l0); split1(a.y,h1,l1); split1(a.z,h2,l2); split1(a.w,h3,l3);
    ((uint2*)(Phi + base))[tid] = make_uint2(pack2(h0,h1), pack2(h2,h3));
    ((uint2*)(Plo + base))[tid] = make_uint2(pack2(l0,l1), pack2(l2,l3));
    split1(b.x,h0,l0); split1(b.y,h1,l1); split1(b.z,h2,l2); split1(b.w,h3,l3);
    ((uint2*)(Phi + base))[tid + 256] = make_uint2(pack2(h0,h1), pack2(h2,h3));
    ((uint2*)(Plo + base))[tid + 256] = make_uint2(pack2(l0,l1), pack2(l2,l3));
}

// ---------------------------------------------------------------------------
// LayerNorm D=1024; optional split emission.
// ---------------------------------------------------------------------------
template<bool SPLIT>
__global__ __launch_bounds__(256) void layernorm_kernel(
    const float* __restrict__ X, const float* __restrict__ g,
    const float* __restrict__ b, float* __restrict__ Y,
    bf16* __restrict__ Yhi, bf16* __restrict__ Ylo)
{
    const float* x = X + (long long)blockIdx.x * D_MODEL;
    int tid = threadIdx.x;
    float4 v = ((const float4*)x)[tid];
    float s = v.x + v.y + v.z + v.w;
    s = block_sum(s);
    float mean = s * (1.0f / D_MODEL);
    float dx=v.x-mean, dy=v.y-mean, dz=v.z-mean, dw=v.w-mean;
    float ss = dx*dx + dy*dy + dz*dz + dw*dw;
    ss = block_sum(ss);
    float rstd = rsqrtf(ss * (1.0f / D_MODEL) + 1e-5f);
    float4 gg = ((const float4*)g)[tid];
    float4 bb = ((const float4*)b)[tid];
    float4 o;
    o.x = dx*rstd*gg.x + bb.x;
    o.y = dy*rstd*gg.y + bb.y;
    o.z = dz*rstd*gg.z + bb.z;
    o.w = dw*rstd*gg.w + bb.w;
    long long base = (long long)blockIdx.x * D_MODEL;
    ((float4*)(Y + base))[tid] = o;
    if (SPLIT) {
        bf16 h0,l0,h1,l1,h2,l2,h3,l3;
        split1(o.x,h0,l0); split1(o.y,h1,l1); split1(o.z,h2,l2); split1(o.w,h3,l3);
        ((uint2*)(Yhi + base))[tid] = make_uint2(pack2(h0,h1), pack2(h2,h3));
        ((uint2*)(Ylo + base))[tid] = make_uint2(pack2(l0,l1), pack2(l2,l3));
    }
}

// ---------------------------------------------------------------------------
// Launch
// ---------------------------------------------------------------------------
extern "C" void kernel_launch(void* const* d_in, const int* in_sizes, int n_in,
                              void* d_out, int out_size)
{
    const float* x     = (const float*)d_in[0];
    const float* wq    = (const float*)d_in[1];
    const float* bq    = (const float*)d_in[2];
    const float* wk    = (const float*)d_in[3];
    const float* bk    = (const float*)d_in[4];
    const float* wv    = (const float*)d_in[5];
    const float* bv    = (const float*)d_in[6];
    const float* wo    = (const float*)d_in[7];
    const float* bo    = (const float*)d_in[8];
    const float* w1    = (const float*)d_in[9];
    const float* b1    = (const float*)d_in[10];
    const float* w2    = (const float*)d_in[11];
    const float* b2    = (const float*)d_in[12];
    const float* g1    = (const float*)d_in[13];
    const float* beta1 = (const float*)d_in[14];
    const float* g2    = (const float*)d_in[15];
    const float* beta2 = (const float*)d_in[16];
    float* out = (float*)d_out;

    #define SYM(p, s) void* p##_; cudaGetSymbolAddress(&p##_, s);
    SYM(xh, g_x_hi)  SYM(xl, g_x_lo)
    SYM(wqh, g_wqT_hi) SYM(wql, g_wqT_lo)
    SYM(wkh, g_wkT_hi) SYM(wkl, g_wkT_lo)
    SYM(wvh, g_wvT_hi) SYM(wvl, g_wvT_lo)
    SYM(woh, g_woT_hi) SYM(wol, g_woT_lo)
    SYM(w1h, g_w1T_hi) SYM(w1l, g_w1T_lo)
    SYM(w2h, g_w2T_hi) SYM(w2l, g_w2T_lo)
    SYM(qh, g_q_hi)  SYM(ql, g_q_lo)
    SYM(kh, g_k_hi)  SYM(kl, g_k_lo)
    SYM(vv, g_v)     SYM(vth, g_vT_hi) SYM(vtl, g_vT_lo)
    SYM(sc, g_s)     SYM(ph, g_p_hi)   SYM(pl, g_p_lo)
    SYM(ch, g_ctx_hi) SYM(cl, g_ctx_lo)
    SYM(x1, g_x1)    SYM(y1, g_y1)  SYM(y1h, g_y1_hi) SYM(y1l, g_y1_lo)
    SYM(hh, g_h_hi)  SYM(hl, g_h_lo)
    SYM(x2, g_x2)
    #undef SYM

    cudaFuncSetAttribute(gemm_nt<1,0,0,0>, cudaFuncAttributeMaxDynamicSharedMemorySize, SMEM_TOTAL);
    cudaFuncSetAttribute(gemm_nt<0,1,0,0>, cudaFuncAttributeMaxDynamicSharedMemorySize, SMEM_TOTAL);
    cudaFuncSetAttribute(gemm_nt<0,1,1,0>, cudaFuncAttributeMaxDynamicSharedMemorySize, SMEM_TOTAL);
    cudaFuncSetAttribute(gemm_nt<1,0,0,1>, cudaFuncAttributeMaxDynamicSharedMemorySize, SMEM_TOTAL);

    dim3 blk(256);

    // 1. split x
    split_kernel<<<M_TOT * D_MODEL / 4 / 256, blk>>>(x, (bf16*)xh_, (bf16*)xl_, M_TOT * D_MODEL / 4);

    // 2. transpose-split weights: src [K,N] -> dst [N,K]
    transpose_split_kernel<<<dim3(D_MODEL/32, D_MODEL/32, 1), blk>>>(wq, (bf16*)wqh_, (bf16*)wql_, D_MODEL, D_MODEL, 0, 0);
    transpose_split_kernel<<<dim3(D_MODEL/32, D_MODEL/32, 1), blk>>>(wk, (bf16*)wkh_, (bf16*)wkl_, D_MODEL, D_MODEL, 0, 0);
    transpose_split_kernel<<<dim3(D_MODEL/32, D_MODEL/32, 1), blk>>>(wv, (bf16*)wvh_, (bf16*)wvl_, D_MODEL, D_MODEL, 0, 0);
    transpose_split_kernel<<<dim3(D_MODEL/32, D_MODEL/32, 1), blk>>>(wo, (bf16*)woh_, (bf16*)wol_, D_MODEL, D_MODEL, 0, 0);
    transpose_split_kernel<<<dim3(FF_DIM/32, D_MODEL/32, 1), blk>>>(w1, (bf16*)w1h_, (bf16*)w1l_, D_MODEL, FF_DIM, 0, 0);
    transpose_split_kernel<<<dim3(D_MODEL/32, FF_DIM/32, 1), blk>>>(w2, (bf16*)w2h_, (bf16*)w2l_, FF_DIM, D_MODEL, 0, 0);

    // 3. q, k (split-out), v (fp32)
    {
        dim3 g(D_MODEL/BN, M_TOT/BM, 1);
        gemm_nt<0,1,0,0><<<g, blk, SMEM_TOTAL>>>((bf16*)xh_, (bf16*)xl_, (bf16*)wqh_, (bf16*)wql_,
            bq, nullptr, nullptr, (bf16*)qh_, (bf16*)ql_, M_TOT, D_MODEL, D_MODEL, 0, 0, 0);
        gemm_nt<0,1,0,0><<<g, blk, SMEM_TOTAL>>>((bf16*)xh_, (bf16*)xl_, (bf16*)wkh_, (bf16*)wkl_,
            bk, nullptr, nullptr, (bf16*)kh_, (bf16*)kl_, M_TOT, D_MODEL, D_MODEL, 0, 0, 0);
        gemm_nt<1,0,0,0><<<g, blk, SMEM_TOTAL>>>((bf16*)xh_, (bf16*)xl_, (bf16*)wvh_, (bf16*)wvl_,
            bv, nullptr, (float*)vv_, nullptr, nullptr, M_TOT, D_MODEL, D_MODEL, 0, 0, 0);
    }

    // 4. vT per batch: [2048,1024] -> [1024,2048]
    transpose_split_kernel<<<dim3(D_MODEL/32, SEQ/32, BATCH), blk>>>((float*)vv_,
        (bf16*)vth_, (bf16*)vtl_, SEQ, D_MODEL, (long long)SEQ*D_MODEL, (long long)SEQ*D_MODEL);

    // 5. scores = q @ k^T (fp32 out)
    gemm_nt<1,0,0,0><<<dim3(SEQ/BN, SEQ/BM, BATCH), blk, SMEM_TOTAL>>>(
        (bf16*)qh_, (bf16*)ql_, (bf16*)kh_, (bf16*)kl_, nullptr, nullptr,
        (float*)sc_, nullptr, nullptr, SEQ, SEQ, D_MODEL,
        (long long)SEQ*D_MODEL, (long long)SEQ*D_MODEL, (long long)SEQ*SEQ);

    // 6. softmax + split
    softmax_split_kernel<<<BATCH*SEQ, blk>>>((float*)sc_, (bf16*)ph_, (bf16*)pl_);

    // 7. ctx = attn @ vT^T (split out)
    gemm_nt<0,1,0,0><<<dim3(D_MODEL/BN, SEQ/BM, BATCH), blk, SMEM_TOTAL>>>(
        (bf16*)ph_, (bf16*)pl_, (bf16*)vth_, (bf16*)vtl_, nullptr, nullptr,
        nullptr, (bf16*)ch_, (bf16*)cl_, SEQ, D_MODEL, SEQ,
        (long long)SEQ*SEQ, (long long)SEQ*D_MODEL, (long long)SEQ*D_MODEL);

    // 8. x1 = x + ctx @ wo^T + bo
    gemm_nt<1,0,0,1><<<dim3(D_MODEL/BN, M_TOT/BM, 1), blk, SMEM_TOTAL>>>(
        (bf16*)ch_, (bf16*)cl_, (bf16*)woh_, (bf16*)wol_, bo, x,
        (float*)x1_, nullptr, nullptr, M_TOT, D_MODEL, D_MODEL, 0, 0, 0);

    // 9. y1 = LN1(x1) + split
    layernorm_kernel<true><<<M_TOT, blk>>>((float*)x1_, g1, beta1, (float*)y1_, (bf16*)y1h_, (bf16*)y1l_);

    // 10. h = relu(y1 @ w1^T + b1) (split out)
    gemm_nt<0,1,1,0><<<dim3(FF_DIM/BN, M_TOT/BM, 1), blk, SMEM_TOTAL>>>(
        (bf16*)y1h_, (bf16*)y1l_, (bf16*)w1h_, (bf16*)w1l_, b1, nullptr,
        nullptr, (bf16*)hh_, (bf16*)hl_, M_TOT, FF_DIM, D_MODEL, 0, 0, 0);

    // 11. x2 = y1 + h @ w2^T + b2
    gemm_nt<1,0,0,1><<<dim3(D_MODEL/BN, M_TOT/BM, 1), blk, SMEM_TOTAL>>>(
        (bf16*)hh_, (bf16*)hl_, (bf16*)w2h_, (bf16*)w2l_, b2, (float*)y1_,
        (float*)x2_, nullptr, nullptr, M_TOT, D_MODEL, FF_DIM, 0, 0, 0);

    // 12. out = LN2(x2)
    layernorm_kernel<false><<<M_TOT, blk>>>((float*)x2_, g2, beta2, out, nullptr, nullptr);
}

// round 4
// speedup vs baseline: 2.4124x; 1.1414x over previous
#include <cuda_runtime.h>
#include <cuda_bf16.h>
#include <math.h>
#include <stdint.h>

// ---------------------------------------------------------------------------
// SmallTransformerBlock via mma.sync bf16x3 split GEMMs (sm_103 baseline PTX).
// R4: 2-stage pipeline + 2 CTAs/SM (was 3-stage/1 CTA), batched weight
// transposes so ncu's launch #5 is a GEMM.
// ---------------------------------------------------------------------------

#define D_MODEL 1024
#define FF_DIM  4096
#define BATCH   4
#define SEQ     2048
#define M_TOT   (BATCH * SEQ)          // 8192

#define BM 128
#define BN 128
#define BK 32
#define STAGES 2
// SMEM row stride 80B (64B data + 16B pad -> conflict-free ldmatrix)
#define ROWB 80
#define OFF_AH 0
#define OFF_AL (128 * ROWB)
#define OFF_BH (2 * 128 * ROWB)
#define OFF_BL (3 * 128 * ROWB)
#define STAGE_BYTES (4 * 128 * ROWB)          // 40960
#define SMEM_TOTAL  (STAGES * STAGE_BYTES)    // 81920

typedef __nv_bfloat16 bf16;

// -------------------------- scratch (device globals) -----------------------
__device__ bf16  g_x_hi [M_TOT * D_MODEL];
__device__ bf16  g_x_lo [M_TOT * D_MODEL];
__device__ bf16  g_wqT_hi[D_MODEL * D_MODEL];
__device__ bf16  g_wqT_lo[D_MODEL * D_MODEL];
__device__ bf16  g_wkT_hi[D_MODEL * D_MODEL];
__device__ bf16  g_wkT_lo[D_MODEL * D_MODEL];
__device__ bf16  g_wvT_hi[D_MODEL * D_MODEL];
__device__ bf16  g_wvT_lo[D_MODEL * D_MODEL];
__device__ bf16  g_woT_hi[D_MODEL * D_MODEL];
__device__ bf16  g_woT_lo[D_MODEL * D_MODEL];
__device__ bf16  g_w1T_hi[FF_DIM * D_MODEL];
__device__ bf16  g_w1T_lo[FF_DIM * D_MODEL];
__device__ bf16  g_w2T_hi[D_MODEL * FF_DIM];
__device__ bf16  g_w2T_lo[D_MODEL * FF_DIM];
__device__ bf16  g_q_hi [M_TOT * D_MODEL];
__device__ bf16  g_q_lo [M_TOT * D_MODEL];
__device__ bf16  g_k_hi [M_TOT * D_MODEL];
__device__ bf16  g_k_lo [M_TOT * D_MODEL];
__device__ float g_v    [M_TOT * D_MODEL];
__device__ bf16  g_vT_hi[M_TOT * D_MODEL];     // [B][D,T]
__device__ bf16  g_vT_lo[M_TOT * D_MODEL];
__device__ float g_s    [BATCH * SEQ * SEQ];
__device__ bf16  g_p_hi [BATCH * SEQ * SEQ];
__device__ bf16  g_p_lo [BATCH * SEQ * SEQ];
__device__ bf16  g_ctx_hi[M_TOT * D_MODEL];
__device__ bf16  g_ctx_lo[M_TOT * D_MODEL];
__device__ float g_x1   [M_TOT * D_MODEL];
__device__ float g_y1   [M_TOT * D_MODEL];
__device__ bf16  g_y1_hi[M_TOT * D_MODEL];
__device__ bf16  g_y1_lo[M_TOT * D_MODEL];
__device__ bf16  g_h_hi [M_TOT * FF_DIM];
__device__ bf16  g_h_lo [M_TOT * FF_DIM];
__device__ float g_x2   [M_TOT * D_MODEL];

// ------------------------------- PTX helpers -------------------------------
__device__ __forceinline__ uint32_t smem_u32(const void* p) {
    uint32_t a;
    asm("{ .reg .u64 t; cvta.to.shared.u64 t, %1; cvt.u32.u64 %0, t; }"
        : "=r"(a) : "l"(p));
    return a;
}
__device__ __forceinline__ void cp16(uint32_t dst, const void* src) {
    asm volatile("cp.async.cg.shared.global [%0], [%1], 16;\n" :: "r"(dst), "l"(src));
}
__device__ __forceinline__ void cp_commit() {
    asm volatile("cp.async.commit_group;\n" ::: "memory");
}
template<int N> __device__ __forceinline__ void cp_wait() {
    asm volatile("cp.async.wait_group %0;\n" :: "n"(N) : "memory");
}
__device__ __forceinline__ void ldsm4(uint32_t& r0, uint32_t& r1, uint32_t& r2,
                                      uint32_t& r3, uint32_t addr) {
    asm volatile("ldmatrix.sync.aligned.m8n8.x4.shared.b16 {%0,%1,%2,%3}, [%4];\n"
                 : "=r"(r0), "=r"(r1), "=r"(r2), "=r"(r3) : "r"(addr));
}
__device__ __forceinline__ void mma16816(float* d, const uint32_t* a, const uint32_t* b) {
    asm volatile(
        "mma.sync.aligned.m16n8k16.row.col.f32.bf16.bf16.f32 "
        "{%0,%1,%2,%3}, {%4,%5,%6,%7}, {%8,%9}, {%0,%1,%2,%3};\n"
        : "+f"(d[0]), "+f"(d[1]), "+f"(d[2]), "+f"(d[3])
        : "r"(a[0]), "r"(a[1]), "r"(a[2]), "r"(a[3]), "r"(b[0]), "r"(b[1]));
}
__device__ __forceinline__ void split1(float v, bf16& h, bf16& l) {
    h = __float2bfloat16(v);
    l = __float2bfloat16(v - __bfloat162float(h));
}
__device__ __forceinline__ uint32_t pack2(bf16 a, bf16 b) {
    return ((uint32_t)__bfloat16_as_ushort(b) << 16) | __bfloat16_as_ushort(a);
}

// ---------------------------------------------------------------------------
// GEMM NT bf16x3: C[M,N] = (Ah+Al) @ (Bh+Bl)^T (+bias)(relu)(+res)
// 128x128x32 tile, 8 warps (warp tile 32x64), 2-stage cp.async, 2 CTAs/SM.
// ---------------------------------------------------------------------------
template<bool F32OUT, bool SPLITOUT, bool RELU, bool HASRES>
__global__ __launch_bounds__(256, 2) void gemm_nt(
    const bf16* __restrict__ Ahi, const bf16* __restrict__ Alo,
    const bf16* __restrict__ Bhi, const bf16* __restrict__ Blo,
    const float* __restrict__ bias, const float* __restrict__ Res,
    float* __restrict__ Cf, bf16* __restrict__ Chi, bf16* __restrict__ Clo,
    int M, int N, int K, long long aS, long long bS, long long cS)
{
    extern __shared__ char smraw[];
    const uint32_t smb = smem_u32(smraw);
    const int tid  = threadIdx.x;
    const int wid  = tid >> 5;
    const int lane = tid & 31;
    const int wm = wid & 3;            // m offset wm*32
    const int wn = wid >> 2;           // n offset wn*64
    const int quad = lane >> 3, lrow = lane & 7;
    const int bz = blockIdx.z;
    const int bm = blockIdx.y * BM;
    const int bn = blockIdx.x * BN;

    const bf16* Ah = Ahi + (long long)bz * aS;
    const bf16* Al = Alo + (long long)bz * aS;
    const bf16* Bh = Bhi + (long long)bz * bS;
    const bf16* Bl = Blo + (long long)bz * bS;

    float acc[2][8][4];
    #pragma unroll
    for (int i = 0; i < 2; i++)
        #pragma unroll
        for (int j = 0; j < 8; j++)
            #pragma unroll
            for (int c = 0; c < 4; c++) acc[i][j][c] = 0.0f;

    const int T = K / BK;

    auto load_stage = [&](int kt, int s) {
        const uint32_t st = smb + s * STAGE_BYTES;
        const int k0 = kt * BK;
        #pragma unroll
        for (int i = 0; i < 2; i++) {
            int id  = tid + i * 256;
            int row = id >> 2, c = id & 3;
            uint32_t off = (uint32_t)(row * ROWB + c * 16);
            long long ga = (long long)(bm + row) * K + k0 + c * 8;
            long long gb = (long long)(bn + row) * K + k0 + c * 8;
            cp16(st + OFF_AH + off, Ah + ga);
            cp16(st + OFF_AL + off, Al + ga);
            cp16(st + OFF_BH + off, Bh + gb);
            cp16(st + OFF_BL + off, Bl + gb);
        }
    };

    auto compute_stage = [&](int s) {
        const uint32_t st = smb + s * STAGE_BYTES;
        #pragma unroll
        for (int ks = 0; ks < 2; ks++) {
            const uint32_t cb = (uint32_t)(ks * 32 + (quad >> 1) * 16);
            uint32_t ah[2][4], al[2][4];
            #pragma unroll
            for (int fm = 0; fm < 2; fm++) {
                uint32_t r = (uint32_t)(wm * 32 + fm * 16 + (quad & 1) * 8 + lrow);
                uint32_t a = st + r * ROWB + cb;
                ldsm4(ah[fm][0], ah[fm][1], ah[fm][2], ah[fm][3], a + OFF_AH);
                ldsm4(al[fm][0], al[fm][1], al[fm][2], al[fm][3], a + OFF_AL);
            }
            #pragma unroll
            for (int g = 0; g < 2; g++) {       // fn groups of 4
                uint32_t bh[4][2], bl[4][2];
                #pragma unroll
                for (int f2 = 0; f2 < 2; f2++) {
                    uint32_t r = (uint32_t)(wn * 64 + (g * 2 + f2) * 16 + (quad & 1) * 8 + lrow);
                    uint32_t a = st + r * ROWB + cb;
                    uint32_t t0, t1, t2, t3;
                    ldsm4(t0, t1, t2, t3, a + OFF_BH);
                    bh[2*f2][0] = t0; bh[2*f2][1] = t2;
                    bh[2*f2+1][0] = t1; bh[2*f2+1][1] = t3;
                    ldsm4(t0, t1, t2, t3, a + OFF_BL);
                    bl[2*f2][0] = t0; bl[2*f2][1] = t2;
                    bl[2*f2+1][0] = t1; bl[2*f2+1][1] = t3;
                }
                #pragma unroll
                for (int fm = 0; fm < 2; fm++)
                    #pragma unroll
                    for (int fn = 0; fn < 4; fn++) {
                        float* d = acc[fm][g * 4 + fn];
                        mma16816(d, ah[fm], bh[fn]);
                        mma16816(d, ah[fm], bl[fn]);
                        mma16816(d, al[fm], bh[fn]);
                    }
            }
        }
    };

    load_stage(0, 0); cp_commit();
    load_stage(1, 1); cp_commit();

    for (int t = 0; t < T; t++) {
        if (t + 2 < T) cp_wait<1>(); else if (t < T - 1) cp_wait<1>(); else cp_wait<0>();
        __syncthreads();
        compute_stage(t & 1);
        __syncthreads();
        if (t + 2 < T) { load_stage(t + 2, t & 1); cp_commit(); }
    }

    // ---------------- epilogue ----------------
    const int groupID = lane >> 2, tIdx = lane & 3;
    #pragma unroll
    for (int fm = 0; fm < 2; fm++) {
        #pragma unroll
        for (int half = 0; half < 2; half++) {
            int row = bm + wm * 32 + fm * 16 + half * 8 + groupID;
            long long rbase = (long long)bz * cS + (long long)row * N;
            #pragma unroll
            for (int fn = 0; fn < 8; fn++) {
                int col = bn + wn * 64 + fn * 8 + tIdx * 2;
                float v0 = acc[fm][fn][half * 2 + 0];
                float v1 = acc[fm][fn][half * 2 + 1];
                if (bias) { v0 += __ldg(bias + col); v1 += __ldg(bias + col + 1); }
                if (RELU) { v0 = fmaxf(v0, 0.0f); v1 = fmaxf(v1, 0.0f); }
                if (HASRES) {
                    float2 rv = *(const float2*)(Res + rbase + col);
                    v0 += rv.x; v1 += rv.y;
                }
                if (F32OUT)
                    *(float2*)(Cf + rbase + col) = make_float2(v0, v1);
                if (SPLITOUT) {
                    bf16 h0, l0, h1, l1;
                    split1(v0, h0, l0); split1(v1, h1, l1);
                    *(uint32_t*)(Chi + rbase + col) = pack2(h0, h1);
                    *(uint32_t*)(Clo + rbase + col) = pack2(l0, l1);
                }
            }
        }
    }
}

// ---------------------------------------------------------------------------
// Elementwise split: fp32 -> (hi, lo) bf16
// ---------------------------------------------------------------------------
__global__ __launch_bounds__(256) void split_kernel(
    const float* __restrict__ src, bf16* __restrict__ hi, bf16* __restrict__ lo, int n4)
{
    int i = blockIdx.x * 256 + threadIdx.x;
    if (i >= n4) return;
    float4 v = ((const float4*)src)[i];
    bf16 h0,l0,h1,l1,h2,l2,h3,l3;
    split1(v.x,h0,l0); split1(v.y,h1,l1); split1(v.z,h2,l2); split1(v.w,h3,l3);
    ((uint2*)hi)[i] = make_uint2(pack2(h0,h1), pack2(h2,h3));
    ((uint2*)lo)[i] = make_uint2(pack2(l0,l1), pack2(l2,l3));
}

// ---------------------------------------------------------------------------
// Transpose-split: src [R,C] fp32 -> dst [C,R] (hi, lo) bf16.
// ---------------------------------------------------------------------------
__global__ __launch_bounds__(256) void transpose_split_kernel(
    const float* __restrict__ src, bf16* __restrict__ hiT, bf16* __restrict__ loT,
    int R, int C, long long sS, long long dS)
{
    __shared__ float tile[32][33];
    const float* S = src + (long long)blockIdx.z * sS;
    int c0 = blockIdx.x * 32, r0 = blockIdx.y * 32;
    int tx = threadIdx.x & 31, ty = threadIdx.x >> 5;   // 32 x 8
    #pragma unroll
    for (int i = 0; i < 32; i += 8)
        tile[ty + i][tx] = S[(long long)(r0 + ty + i) * C + c0 + tx];
    __syncthreads();
    #pragma unroll
    for (int i = 0; i < 32; i += 8) {
        float v = tile[tx][ty + i];
        bf16 h, l; split1(v, h, l);
        long long o = (long long)blockIdx.z * dS + (long long)(c0 + ty + i) * R + r0 + tx;
        hiT[o] = h; loT[o] = l;
    }
}

// Batched version for the four 1024x1024 weights: z picks the weight.
__global__ __launch_bounds__(256) void transpose_split4_kernel(
    const float* __restrict__ s0, const float* __restrict__ s1,
    const float* __restrict__ s2, const float* __restrict__ s3,
    bf16* __restrict__ h0, bf16* __restrict__ l0,
    bf16* __restrict__ h1, bf16* __restrict__ l1,
    bf16* __restrict__ h2, bf16* __restrict__ l2,
    bf16* __restrict__ h3, bf16* __restrict__ l3)
{
    __shared__ float tile[32][33];
    const int z = blockIdx.z;
    const float* S = (z == 0) ? s0 : (z == 1) ? s1 : (z == 2) ? s2 : s3;
    bf16* H = (z == 0) ? h0 : (z == 1) ? h1 : (z == 2) ? h2 : h3;
    bf16* L = (z == 0) ? l0 : (z == 1) ? l1 : (z == 2) ? l2 : l3;
    int c0 = blockIdx.x * 32, r0 = blockIdx.y * 32;
    int tx = threadIdx.x & 31, ty = threadIdx.x >> 5;
    #pragma unroll
    for (int i = 0; i < 32; i += 8)
        tile[ty + i][tx] = S[(long long)(r0 + ty + i) * D_MODEL + c0 + tx];
    __syncthreads();
    #pragma unroll
    for (int i = 0; i < 32; i += 8) {
        float v = tile[tx][ty + i];
        bf16 h, l; split1(v, h, l);
        long long o = (long long)(c0 + ty + i) * D_MODEL + r0 + tx;
        H[o] = h; L[o] = l;
    }
}

// ------------------------------- reductions --------------------------------
__device__ __forceinline__ float block_sum(float v) {
    __shared__ float sh[8];
    int lane = threadIdx.x & 31, w = threadIdx.x >> 5;
    #pragma unroll
    for (int o = 16; o > 0; o >>= 1) v += __shfl_xor_sync(0xffffffffu, v, o);
    if (lane == 0) sh[w] = v;
    __syncthreads();
    if (w == 0) {
        float t = (lane < 8) ? sh[lane] : 0.0f;
        #pragma unroll
        for (int o = 4; o > 0; o >>= 1) t += __shfl_xor_sync(0xffffffffu, t, o);
        if (lane == 0) sh[0] = t;
    }
    __syncthreads();
    float r = sh[0];
    __syncthreads();
    return r;
}
__device__ __forceinline__ float block_max(float v) {
    __shared__ float sh[8];
    int lane = threadIdx.x & 31, w = threadIdx.x >> 5;
    #pragma unroll
    for (int o = 16; o > 0; o >>= 1) v = fmaxf(v, __shfl_xor_sync(0xffffffffu, v, o));
    if (lane == 0) sh[w] = v;
    __syncthreads();
    if (w == 0) {
        float t = (lane < 8) ? sh[lane] : -3.4e38f;
        #pragma unroll
        for (int o = 4; o > 0; o >>= 1) t = fmaxf(t, __shfl_xor_sync(0xffffffffu, t, o));
        if (lane == 0) sh[0] = t;
    }
    __syncthreads();
    float r = sh[0];
    __syncthreads();
    return r;
}

// ---------------------------------------------------------------------------
// Softmax over SEQ=2048 with fused 1/scale; outputs pre-split hi/lo bf16.
// ---------------------------------------------------------------------------
__global__ __launch_bounds__(256) void softmax_split_kernel(
    const float* __restrict__ S, bf16* __restrict__ Phi, bf16* __restrict__ Plo)
{
    const float inv_scale = 0.0883883476483184f;  // 1/sqrt(128)
    const float* row = S + (long long)blockIdx.x * SEQ;
    int tid = threadIdx.x;

    float4 a = ((const float4*)row)[tid];
    float4 b = ((const float4*)row)[tid + 256];
    a.x*=inv_scale; a.y*=inv_scale; a.z*=inv_scale; a.w*=inv_scale;
    b.x*=inv_scale; b.y*=inv_scale; b.z*=inv_scale; b.w*=inv_scale;

    float m = fmaxf(fmaxf(fmaxf(a.x,a.y), fmaxf(a.z,a.w)),
                    fmaxf(fmaxf(b.x,b.y), fmaxf(b.z,b.w)));
    m = block_max(m);
    a.x=expf(a.x-m); a.y=expf(a.y-m); a.z=expf(a.z-m); a.w=expf(a.w-m);
    b.x=expf(b.x-m); b.y=expf(b.y-m); b.z=expf(b.z-m); b.w=expf(b.w-m);
    float s = a.x+a.y+a.z+a.w + b.x+b.y+b.z+b.w;
    s = block_sum(s);
    float inv = 1.0f / s;
    a.x*=inv; a.y*=inv; a.z*=inv; a.w*=inv;
    b.x*=inv; b.y*=inv; b.z*=inv; b.w*=inv;

    long long base = (long long)blockIdx.x * SEQ;
    bf16 h0,l0,h1,l1,h2,l2,h3,l3;
    split1(a.x,h0,l0); split1(a.y,h1,l1); split1(a.z,h2,l2); split1(a.w,h3,l3);
    ((uint2*)(Phi + base))[tid] = make_uint2(pack2(h0,h1), pack2(h2,h3));
    ((uint2*)(Plo + base))[tid] = make_uint2(pack2(l0,l1), pack2(l2,l3));
    split1(b.x,h0,l0); split1(b.y,h1,l1); split1(b.z,h2,l2); split1(b.w,h3,l3);
    ((uint2*)(Phi + base))[tid + 256] = make_uint2(pack2(h0,h1), pack2(h2,h3));
    ((uint2*)(Plo + base))[tid + 256] = make_uint2(pack2(l0,l1), pack2(l2,l3));
}

// ---------------------------------------------------------------------------
// LayerNorm D=1024; optional split emission.
// ---------------------------------------------------------------------------
template<bool SPLIT>
__global__ __launch_bounds__(256) void layernorm_kernel(
    const float* __restrict__ X, const float* __restrict__ g,
    const float* __restrict__ b, float* __restrict__ Y,
    bf16* __restrict__ Yhi, bf16* __restrict__ Ylo)
{
    const float* x = X + (long long)blockIdx.x * D_MODEL;
    int tid = threadIdx.x;
    float4 v = ((const float4*)x)[tid];
    float s = v.x + v.y + v.z + v.w;
    s = block_sum(s);
    float mean = s * (1.0f / D_MODEL);
    float dx=v.x-mean, dy=v.y-mean, dz=v.z-mean, dw=v.w-mean;
    float ss = dx*dx + dy*dy + dz*dz + dw*dw;
    ss = block_sum(ss);
    float rstd = rsqrtf(ss * (1.0f / D_MODEL) + 1e-5f);
    float4 gg = ((const float4*)g)[tid];
    float4 bb = ((const float4*)b)[tid];
    float4 o;
    o.x = dx*rstd*gg.x + bb.x;
    o.y = dy*rstd*gg.y + bb.y;
    o.z = dz*rstd*gg.z + bb.z;
    o.w = dw*rstd*gg.w + bb.w;
    long long base = (long long)blockIdx.x * D_MODEL;
    ((float4*)(Y + base))[tid] = o;
    if (SPLIT) {
        bf16 h0,l0,h1,l1,h2,l2,h3,l3;
        split1(o.x,h0,l0); split1(o.y,h1,l1); split1(o.z,h2,l2); split1(o.w,h3,l3);
        ((uint2*)(Yhi + base))[tid] = make_uint2(pack2(h0,h1), pack2(h2,h3));
        ((uint2*)(Ylo + base))[tid] = make_uint2(pack2(l0,l1), pack2(l2,l3));
    }
}

// ---------------------------------------------------------------------------
// Launch
// ---------------------------------------------------------------------------
extern "C" void kernel_launch(void* const* d_in, const int* in_sizes, int n_in,
                              void* d_out, int out_size)
{
    const float* x     = (const float*)d_in[0];
    const float* wq    = (const float*)d_in[1];
    const float* bq    = (const float*)d_in[2];
    const float* wk    = (const float*)d_in[3];
    const float* bk    = (const float*)d_in[4];
    const float* wv    = (const float*)d_in[5];
    const float* bv    = (const float*)d_in[6];
    const float* wo    = (const float*)d_in[7];
    const float* bo    = (const float*)d_in[8];
    const float* w1    = (const float*)d_in[9];
    const float* b1    = (const float*)d_in[10];
    const float* w2    = (const float*)d_in[11];
    const float* b2    = (const float*)d_in[12];
    const float* g1    = (const float*)d_in[13];
    const float* beta1 = (const float*)d_in[14];
    const float* g2    = (const float*)d_in[15];
    const float* beta2 = (const float*)d_in[16];
    float* out = (float*)d_out;

    #define SYM(p, s) void* p##_; cudaGetSymbolAddress(&p##_, s);
    SYM(xh, g_x_hi)  SYM(xl, g_x_lo)
    SYM(wqh, g_wqT_hi) SYM(wql, g_wqT_lo)
    SYM(wkh, g_wkT_hi) SYM(wkl, g_wkT_lo)
    SYM(wvh, g_wvT_hi) SYM(wvl, g_wvT_lo)
    SYM(woh, g_woT_hi) SYM(wol, g_woT_lo)
    SYM(w1h, g_w1T_hi) SYM(w1l, g_w1T_lo)
    SYM(w2h, g_w2T_hi) SYM(w2l, g_w2T_lo)
    SYM(qh, g_q_hi)  SYM(ql, g_q_lo)
    SYM(kh, g_k_hi)  SYM(kl, g_k_lo)
    SYM(vv, g_v)     SYM(vth, g_vT_hi) SYM(vtl, g_vT_lo)
    SYM(sc, g_s)     SYM(ph, g_p_hi)   SYM(pl, g_p_lo)
    SYM(ch, g_ctx_hi) SYM(cl, g_ctx_lo)
    SYM(x1, g_x1)    SYM(y1, g_y1)  SYM(y1h, g_y1_hi) SYM(y1l, g_y1_lo)
    SYM(hh, g_h_hi)  SYM(hl, g_h_lo)
    SYM(x2, g_x2)
    #undef SYM

    cudaFuncSetAttribute(gemm_nt<1,0,0,0>, cudaFuncAttributeMaxDynamicSharedMemorySize, SMEM_TOTAL);
    cudaFuncSetAttribute(gemm_nt<0,1,0,0>, cudaFuncAttributeMaxDynamicSharedMemorySize, SMEM_TOTAL);
    cudaFuncSetAttribute(gemm_nt<0,1,1,0>, cudaFuncAttributeMaxDynamicSharedMemorySize, SMEM_TOTAL);
    cudaFuncSetAttribute(gemm_nt<1,0,0,1>, cudaFuncAttributeMaxDynamicSharedMemorySize, SMEM_TOTAL);

    dim3 blk(256);

    // 0. split x
    split_kernel<<<M_TOT * D_MODEL / 4 / 256, blk>>>(x, (bf16*)xh_, (bf16*)xl_, M_TOT * D_MODEL / 4);

    // 1. transpose-split the four DxD weights in one launch
    transpose_split4_kernel<<<dim3(D_MODEL/32, D_MODEL/32, 4), blk>>>(
        wq, wk, wv, wo,
        (bf16*)wqh_, (bf16*)wql_, (bf16*)wkh_, (bf16*)wkl_,
        (bf16*)wvh_, (bf16*)wvl_, (bf16*)woh_, (bf16*)wol_);

    // 2-3. w1, w2 transposes
    transpose_split_kernel<<<dim3(FF_DIM/32, D_MODEL/32, 1), blk>>>(w1, (bf16*)w1h_, (bf16*)w1l_, D_MODEL, FF_DIM, 0, 0);
    transpose_split_kernel<<<dim3(D_MODEL/32, FF_DIM/32, 1), blk>>>(w2, (bf16*)w2h_, (bf16*)w2l_, FF_DIM, D_MODEL, 0, 0);

    // 4-6. q, k (split-out), v (fp32)
    {
        dim3 g(D_MODEL/BN, M_TOT/BM, 1);
        gemm_nt<0,1,0,0><<<g, blk, SMEM_TOTAL>>>((bf16*)xh_, (bf16*)xl_, (bf16*)wqh_, (bf16*)wql_,
            bq, nullptr, nullptr, (bf16*)qh_, (bf16*)ql_, M_TOT, D_MODEL, D_MODEL, 0, 0, 0);
        gemm_nt<0,1,0,0><<<g, blk, SMEM_TOTAL>>>((bf16*)xh_, (bf16*)xl_, (bf16*)wkh_, (bf16*)wkl_,
            bk, nullptr, nullptr, (bf16*)kh_, (bf16*)kl_, M_TOT, D_MODEL, D_MODEL, 0, 0, 0);
        gemm_nt<1,0,0,0><<<g, blk, SMEM_TOTAL>>>((bf16*)xh_, (bf16*)xl_, (bf16*)wvh_, (bf16*)wvl_,
            bv, nullptr, (float*)vv_, nullptr, nullptr, M_TOT, D_MODEL, D_MODEL, 0, 0, 0);
    }

    // 7. vT per batch: [2048,1024] -> [1024,2048]
    transpose_split_kernel<<<dim3(D_MODEL/32, SEQ/32, BATCH), blk>>>((float*)vv_,
        (bf16*)vth_, (bf16*)vtl_, SEQ, D_MODEL, (long long)SEQ*D_MODEL, (long long)SEQ*D_MODEL);

    // 8. scores = q @ k^T (fp32 out)
    gemm_nt<1,0,0,0><<<dim3(SEQ/BN, SEQ/BM, BATCH), blk, SMEM_TOTAL>>>(
        (bf16*)qh_, (bf16*)ql_, (bf16*)kh_, (bf16*)kl_, nullptr, nullptr,
        (float*)sc_, nullptr, nullptr, SEQ, SEQ, D_MODEL,
        (long long)SEQ*D_MODEL, (long long)SEQ*D_MODEL, (long long)SEQ*SEQ);

    // 9. softmax + split
    softmax_split_kernel<<<BATCH*SEQ, blk>>>((float*)sc_, (bf16*)ph_, (bf16*)pl_);

    // 10. ctx = attn @ vT^T (split out)
    gemm_nt<0,1,0,0><<<dim3(D_MODEL/BN, SEQ/BM, BATCH), blk, SMEM_TOTAL>>>(
        (bf16*)ph_, (bf16*)pl_, (bf16*)vth_, (bf16*)vtl_, nullptr, nullptr,
        nullptr, (bf16*)ch_, (bf16*)cl_, SEQ, D_MODEL, SEQ,
        (long long)SEQ*SEQ, (long long)SEQ*D_MODEL, (long long)SEQ*D_MODEL);

    // 11. x1 = x + ctx @ wo^T + bo
    gemm_nt<1,0,0,1><<<dim3(D_MODEL/BN, M_TOT/BM, 1), blk, SMEM_TOTAL>>>(
        (bf16*)ch_, (bf16*)cl_, (bf16*)woh_, (bf16*)wol_, bo, x,
        (float*)x1_, nullptr, nullptr, M_TOT, D_MODEL, D_MODEL, 0, 0, 0);

    // 12. y1 = LN1(x1) + split
    layernorm_kernel<true><<<M_TOT, blk>>>((float*)x1_, g1, beta1, (float*)y1_, (bf16*)y1h_, (bf16*)y1l_);

    // 13. h = relu(y1 @ w1^T + b1) (split out)
    gemm_nt<0,1,1,0><<<dim3(FF_DIM/BN, M_TOT/BM, 1), blk, SMEM_TOTAL>>>(
        (bf16*)y1h_, (bf16*)y1l_, (bf16*)w1h_, (bf16*)w1l_, b1, nullptr,
        nullptr, (bf16*)hh_, (bf16*)hl_, M_TOT, FF_DIM, D_MODEL, 0, 0, 0);

    // 14. x2 = y1 + h @ w2^T + b2
    gemm_nt<1,0,0,1><<<dim3(D_MODEL/BN, M_TOT/BM, 1), blk, SMEM_TOTAL>>>(
        (bf16*)hh_, (bf16*)hl_, (bf16*)w2h_, (bf16*)w2l_, b2, (float*)y1_,
        (float*)x2_, nullptr, nullptr, M_TOT, D_MODEL, FF_DIM, 0, 0, 0);

    // 15. out = LN2(x2)
    layernorm_kernel<false><<<M_TOT, blk>>>((float*)x2_, g2, beta2, out, nullptr, nullptr);
}

// round 5
// speedup vs baseline: 2.5565x; 1.0597x over previous
#include <cuda_runtime.h>
#include <cuda_bf16.h>
#include <math.h>
#include <stdint.h>

// ---------------------------------------------------------------------------
// SmallTransformerBlock via mma.sync bf16x3 split GEMMs (sm_103 baseline PTX).
// R5: SW128-swizzled SMEM (hi/lo packed per 128B row, conflict-free ldmatrix),
// 3-stage cp.async pipeline, 1 syncthreads/stage, 2 CTAs/SM.
// ---------------------------------------------------------------------------

#define D_MODEL 1024
#define FF_DIM  4096
#define BATCH   4
#define SEQ     2048
#define M_TOT   (BATCH * SEQ)          // 8192

#define BM 128
#define BN 128
#define BK 32
#define STAGES 3
// Row = 128B: chunks 0-3 hi (32 k bf16), chunks 4-7 lo. A buf 16KB + B buf 16KB.
#define ABUF_BYTES (128 * 128)
#define STAGE_BYTES (2 * ABUF_BYTES)          // 32768
#define SMEM_TOTAL  (STAGES * STAGE_BYTES)    // 98304

typedef __nv_bfloat16 bf16;

// -------------------------- scratch (device globals) -----------------------
__device__ bf16  g_x_hi [M_TOT * D_MODEL];
__device__ bf16  g_x_lo [M_TOT * D_MODEL];
__device__ bf16  g_wqT_hi[D_MODEL * D_MODEL];
__device__ bf16  g_wqT_lo[D_MODEL * D_MODEL];
__device__ bf16  g_wkT_hi[D_MODEL * D_MODEL];
__device__ bf16  g_wkT_lo[D_MODEL * D_MODEL];
__device__ bf16  g_wvT_hi[D_MODEL * D_MODEL];
__device__ bf16  g_wvT_lo[D_MODEL * D_MODEL];
__device__ bf16  g_woT_hi[D_MODEL * D_MODEL];
__device__ bf16  g_woT_lo[D_MODEL * D_MODEL];
__device__ bf16  g_w1T_hi[FF_DIM * D_MODEL];
__device__ bf16  g_w1T_lo[FF_DIM * D_MODEL];
__device__ bf16  g_w2T_hi[D_MODEL * FF_DIM];
__device__ bf16  g_w2T_lo[D_MODEL * FF_DIM];
__device__ bf16  g_q_hi [M_TOT * D_MODEL];
__device__ bf16  g_q_lo [M_TOT * D_MODEL];
__device__ bf16  g_k_hi [M_TOT * D_MODEL];
__device__ bf16  g_k_lo [M_TOT * D_MODEL];
__device__ float g_v    [M_TOT * D_MODEL];
__device__ bf16  g_vT_hi[M_TOT * D_MODEL];     // [B][D,T]
__device__ bf16  g_vT_lo[M_TOT * D_MODEL];
__device__ float g_s    [BATCH * SEQ * SEQ];
__device__ bf16  g_p_hi [BATCH * SEQ * SEQ];
__device__ bf16  g_p_lo [BATCH * SEQ * SEQ];
__device__ bf16  g_ctx_hi[M_TOT * D_MODEL];
__device__ bf16  g_ctx_lo[M_TOT * D_MODEL];
__device__ float g_x1   [M_TOT * D_MODEL];
__device__ float g_y1   [M_TOT * D_MODEL];
__device__ bf16  g_y1_hi[M_TOT * D_MODEL];
__device__ bf16  g_y1_lo[M_TOT * D_MODEL];
__device__ bf16  g_h_hi [M_TOT * FF_DIM];
__device__ bf16  g_h_lo [M_TOT * FF_DIM];
__device__ float g_x2   [M_TOT * D_MODEL];

// ------------------------------- PTX helpers -------------------------------
__device__ __forceinline__ uint32_t smem_u32(const void* p) {
    uint32_t a;
    asm("{ .reg .u64 t; cvta.to.shared.u64 t, %1; cvt.u32.u64 %0, t; }"
        : "=r"(a) : "l"(p));
    return a;
}
__device__ __forceinline__ void cp16(uint32_t dst, const void* src) {
    asm volatile("cp.async.cg.shared.global [%0], [%1], 16;\n" :: "r"(dst), "l"(src));
}
__device__ __forceinline__ void cp_commit() {
    asm volatile("cp.async.commit_group;\n" ::: "memory");
}
template<int N> __device__ __forceinline__ void cp_wait() {
    asm volatile("cp.async.wait_group %0;\n" :: "n"(N) : "memory");
}
__device__ __forceinline__ void ldsm4(uint32_t& r0, uint32_t& r1, uint32_t& r2,
                                      uint32_t& r3, uint32_t addr) {
    asm volatile("ldmatrix.sync.aligned.m8n8.x4.shared.b16 {%0,%1,%2,%3}, [%4];\n"
                 : "=r"(r0), "=r"(r1), "=r"(r2), "=r"(r3) : "r"(addr));
}
__device__ __forceinline__ void mma16816(float* d, const uint32_t* a, const uint32_t* b) {
    asm volatile(
        "mma.sync.aligned.m16n8k16.row.col.f32.bf16.bf16.f32 "
        "{%0,%1,%2,%3}, {%4,%5,%6,%7}, {%8,%9}, {%0,%1,%2,%3};\n"
        : "+f"(d[0]), "+f"(d[1]), "+f"(d[2]), "+f"(d[3])
        : "r"(a[0]), "r"(a[1]), "r"(a[2]), "r"(a[3]), "r"(b[0]), "r"(b[1]));
}
__device__ __forceinline__ void split1(float v, bf16& h, bf16& l) {
    h = __float2bfloat16(v);
    l = __float2bfloat16(v - __bfloat162float(h));
}
__device__ __forceinline__ uint32_t pack2(bf16 a, bf16 b) {
    return ((uint32_t)__bfloat16_as_ushort(b) << 16) | __bfloat16_as_ushort(a);
}

// ---------------------------------------------------------------------------
// GEMM NT bf16x3: C[M,N] = (Ah+Al) @ (Bh+Bl)^T (+bias)(relu)(+res)
// 128x128x32 tile, 8 warps (warp tile 32x64), 3-stage cp.async, 2 CTAs/SM.
// SMEM row = 128B SW128-swizzled: chunks 0-3 = hi k0..31, chunks 4-7 = lo.
// ---------------------------------------------------------------------------
template<bool F32OUT, bool SPLITOUT, bool RELU, bool HASRES>
__global__ __launch_bounds__(256, 2) void gemm_nt(
    const bf16* __restrict__ Ahi, const bf16* __restrict__ Alo,
    const bf16* __restrict__ Bhi, const bf16* __restrict__ Blo,
    const float* __restrict__ bias, const float* __restrict__ Res,
    float* __restrict__ Cf, bf16* __restrict__ Chi, bf16* __restrict__ Clo,
    int M, int N, int K, long long aS, long long bS, long long cS)
{
    extern __shared__ char smraw[];
    const uint32_t smb = smem_u32(smraw);
    const int tid  = threadIdx.x;
    const int wid  = tid >> 5;
    const int lane = tid & 31;
    const int wm = wid & 3;            // m offset wm*32
    const int wn = wid >> 2;           // n offset wn*64
    const int quad = lane >> 3, lrow = lane & 7;
    const int bz = blockIdx.z;
    const int bm = blockIdx.y * BM;
    const int bn = blockIdx.x * BN;

    const bf16* Ah = Ahi + (long long)bz * aS;
    const bf16* Al = Alo + (long long)bz * aS;
    const bf16* Bh = Bhi + (long long)bz * bS;
    const bf16* Bl = Blo + (long long)bz * bS;

    float acc[2][8][4];
    #pragma unroll
    for (int i = 0; i < 2; i++)
        #pragma unroll
        for (int j = 0; j < 8; j++)
            #pragma unroll
            for (int c = 0; c < 4; c++) acc[i][j][c] = 0.0f;

    const int T = K / BK;

    // per-thread constant load mapping: 8 chunks/thread, c fixed = tid&7
    const int lc   = tid & 7;              // chunk 0-7
    const bool lhi = (lc < 4);
    const int lk   = (lhi ? lc : lc - 4) * 8;   // k element offset within BK

    auto load_stage = [&](int kt, int s) {
        const uint32_t st = smb + s * STAGE_BYTES;
        const int k0 = kt * BK;
        #pragma unroll
        for (int i = 0; i < 8; i++) {
            int id  = tid + i * 256;       // 0..2047
            int buf = id >> 10;            // 0=A, 1=B
            int row = (id >> 3) & 127;
            uint32_t dst = st + (uint32_t)buf * ABUF_BYTES
                         + (uint32_t)(row * 128 + ((lc ^ (row & 7)) * 16));
            const bf16* base = buf
                ? (lhi ? Bh : Bl) : (lhi ? Ah : Al);
            long long g = (long long)((buf ? bn : bm) + row) * K + k0 + lk;
            cp16(dst, base + g);
        }
    };

    auto compute_stage = [&](int s) {
        const uint32_t stA = smb + s * STAGE_BYTES;
        const uint32_t stB = stA + ABUF_BYTES;
        #pragma unroll
        for (int ks = 0; ks < 2; ks++) {
            const int chnk_hi = ks * 2 + (quad >> 1);   // 0-3
            uint32_t ah[2][4], al[2][4];
            #pragma unroll
            for (int fm = 0; fm < 2; fm++) {
                int r = wm * 32 + fm * 16 + (quad & 1) * 8 + lrow;
                uint32_t ah_addr = stA + (uint32_t)(r * 128 + ((chnk_hi ^ (r & 7)) * 16));
                uint32_t al_addr = stA + (uint32_t)(r * 128 + (((chnk_hi + 4) ^ (r & 7)) * 16));
                ldsm4(ah[fm][0], ah[fm][1], ah[fm][2], ah[fm][3], ah_addr);
                ldsm4(al[fm][0], al[fm][1], al[fm][2], al[fm][3], al_addr);
            }
            #pragma unroll
            for (int g = 0; g < 2; g++) {       // fn groups of 4
                uint32_t bh[4][2], bl[4][2];
                #pragma unroll
                for (int f2 = 0; f2 < 2; f2++) {
                    int r = wn * 64 + (g * 2 + f2) * 16 + (quad & 1) * 8 + lrow;
                    uint32_t bh_addr = stB + (uint32_t)(r * 128 + ((chnk_hi ^ (r & 7)) * 16));
                    uint32_t bl_addr = stB + (uint32_t)(r * 128 + (((chnk_hi + 4) ^ (r & 7)) * 16));
                    uint32_t t0, t1, t2, t3;
                    ldsm4(t0, t1, t2, t3, bh_addr);
                    bh[2*f2][0] = t0; bh[2*f2][1] = t2;
                    bh[2*f2+1][0] = t1; bh[2*f2+1][1] = t3;
                    ldsm4(t0, t1, t2, t3, bl_addr);
                    bl[2*f2][0] = t0; bl[2*f2][1] = t2;
                    bl[2*f2+1][0] = t1; bl[2*f2+1][1] = t3;
                }
                #pragma unroll
                for (int fm = 0; fm < 2; fm++)
                    #pragma unroll
                    for (int fn = 0; fn < 4; fn++) {
                        float* d = acc[fm][g * 4 + fn];
                        mma16816(d, ah[fm], bh[fn]);
                        mma16816(d, ah[fm], bl[fn]);
                        mma16816(d, al[fm], bh[fn]);
                    }
            }
        }
    };

    load_stage(0, 0); cp_commit();
    load_stage(1, 1); cp_commit();

    for (int t = 0; t < T; t++) {
        if (t < T - 1) cp_wait<1>(); else cp_wait<0>();
        __syncthreads();
        if (t + 2 < T) { load_stage(t + 2, (t + 2) % STAGES); cp_commit(); }
        compute_stage(t % STAGES);
    }

    // ---------------- epilogue ----------------
    const int groupID = lane >> 2, tIdx = lane & 3;
    #pragma unroll
    for (int fm = 0; fm < 2; fm++) {
        #pragma unroll
        for (int half = 0; half < 2; half++) {
            int row = bm + wm * 32 + fm * 16 + half * 8 + groupID;
            long long rbase = (long long)bz * cS + (long long)row * N;
            #pragma unroll
            for (int fn = 0; fn < 8; fn++) {
                int col = bn + wn * 64 + fn * 8 + tIdx * 2;
                float v0 = acc[fm][fn][half * 2 + 0];
                float v1 = acc[fm][fn][half * 2 + 1];
                if (bias) { v0 += __ldg(bias + col); v1 += __ldg(bias + col + 1); }
                if (RELU) { v0 = fmaxf(v0, 0.0f); v1 = fmaxf(v1, 0.0f); }
                if (HASRES) {
                    float2 rv = *(const float2*)(Res + rbase + col);
                    v0 += rv.x; v1 += rv.y;
                }
                if (F32OUT)
                    *(float2*)(Cf + rbase + col) = make_float2(v0, v1);
                if (SPLITOUT) {
                    bf16 h0, l0, h1, l1;
                    split1(v0, h0, l0); split1(v1, h1, l1);
                    *(uint32_t*)(Chi + rbase + col) = pack2(h0, h1);
                    *(uint32_t*)(Clo + rbase + col) = pack2(l0, l1);
                }
            }
        }
    }
}

// ---------------------------------------------------------------------------
// Elementwise split: fp32 -> (hi, lo) bf16
// ---------------------------------------------------------------------------
__global__ __launch_bounds__(256) void split_kernel(
    const float* __restrict__ src, bf16* __restrict__ hi, bf16* __restrict__ lo, int n4)
{
    int i = blockIdx.x * 256 + threadIdx.x;
    if (i >= n4) return;
    float4 v = ((const float4*)src)[i];
    bf16 h0,l0,h1,l1,h2,l2,h3,l3;
    split1(v.x,h0,l0); split1(v.y,h1,l1); split1(v.z,h2,l2); split1(v.w,h3,l3);
    ((uint2*)hi)[i] = make_uint2(pack2(h0,h1), pack2(h2,h3));
    ((uint2*)lo)[i] = make_uint2(pack2(l0,l1), pack2(l2,l3));
}

// ---------------------------------------------------------------------------
// Transpose-split: src [R,C] fp32 -> dst [C,R] (hi, lo) bf16.
// ---------------------------------------------------------------------------
__global__ __launch_bounds__(256) void transpose_split_kernel(
    const float* __restrict__ src, bf16* __restrict__ hiT, bf16* __restrict__ loT,
    int R, int C, long long sS, long long dS)
{
    __shared__ float tile[32][33];
    const float* S = src + (long long)blockIdx.z * sS;
    int c0 = blockIdx.x * 32, r0 = blockIdx.y * 32;
    int tx = threadIdx.x & 31, ty = threadIdx.x >> 5;   // 32 x 8
    #pragma unroll
    for (int i = 0; i < 32; i += 8)
        tile[ty + i][tx] = S[(long long)(r0 + ty + i) * C + c0 + tx];
    __syncthreads();
    #pragma unroll
    for (int i = 0; i < 32; i += 8) {
        float v = tile[tx][ty + i];
        bf16 h, l; split1(v, h, l);
        long long o = (long long)blockIdx.z * dS + (long long)(c0 + ty + i) * R + r0 + tx;
        hiT[o] = h; loT[o] = l;
    }
}

// Batched version for the four 1024x1024 weights: z picks the weight.
__global__ __launch_bounds__(256) void transpose_split4_kernel(
    const float* __restrict__ s0, const float* __restrict__ s1,
    const float* __restrict__ s2, const float* __restrict__ s3,
    bf16* __restrict__ h0, bf16* __restrict__ l0,
    bf16* __restrict__ h1, bf16* __restrict__ l1,
    bf16* __restrict__ h2, bf16* __restrict__ l2,
    bf16* __restrict__ h3, bf16* __restrict__ l3)
{
    __shared__ float tile[32][33];
    const int z = blockIdx.z;
    const float* S = (z == 0) ? s0 : (z == 1) ? s1 : (z == 2) ? s2 : s3;
    bf16* H = (z == 0) ? h0 : (z == 1) ? h1 : (z == 2) ? h2 : h3;
    bf16* L = (z == 0) ? l0 : (z == 1) ? l1 : (z == 2) ? l2 : l3;
    int c0 = blockIdx.x * 32, r0 = blockIdx.y * 32;
    int tx = threadIdx.x & 31, ty = threadIdx.x >> 5;
    #pragma unroll
    for (int i = 0; i < 32; i += 8)
        tile[ty + i][tx] = S[(long long)(r0 + ty + i) * D_MODEL + c0 + tx];
    __syncthreads();
    #pragma unroll
    for (int i = 0; i < 32; i += 8) {
        float v = tile[tx][ty + i];
        bf16 h, l; split1(v, h, l);
        long long o = (long long)(c0 + ty + i) * D_MODEL + r0 + tx;
        H[o] = h; L[o] = l;
    }
}

// ------------------------------- reductions --------------------------------
__device__ __forceinline__ float block_sum(float v) {
    __shared__ float sh[8];
    int lane = threadIdx.x & 31, w = threadIdx.x >> 5;
    #pragma unroll
    for (int o = 16; o > 0; o >>= 1) v += __shfl_xor_sync(0xffffffffu, v, o);
    if (lane == 0) sh[w] = v;
    __syncthreads();
    if (w == 0) {
        float t = (lane < 8) ? sh[lane] : 0.0f;
        #pragma unroll
        for (int o = 4; o > 0; o >>= 1) t += __shfl_xor_sync(0xffffffffu, t, o);
        if (lane == 0) sh[0] = t;
    }
    __syncthreads();
    float r = sh[0];
    __syncthreads();
    return r;
}
__device__ __forceinline__ float block_max(float v) {
    __shared__ float sh[8];
    int lane = threadIdx.x & 31, w = threadIdx.x >> 5;
    #pragma unroll
    for (int o = 16; o > 0; o >>= 1) v = fmaxf(v, __shfl_xor_sync(0xffffffffu, v, o));
    if (lane == 0) sh[w] = v;
    __syncthreads();
    if (w == 0) {
        float t = (lane < 8) ? sh[lane] : -3.4e38f;
        #pragma unroll
        for (int o = 4; o > 0; o >>= 1) t = fmaxf(t, __shfl_xor_sync(0xffffffffu, t, o));
        if (lane == 0) sh[0] = t;
    }
    __syncthreads();
    float r = sh[0];
    __syncthreads();
    return r;
}

// ---------------------------------------------------------------------------
// Softmax over SEQ=2048 with fused 1/scale; outputs pre-split hi/lo bf16.
// ---------------------------------------------------------------------------
__global__ __launch_bounds__(256) void softmax_split_kernel(
    const float* __restrict__ S, bf16* __restrict__ Phi, bf16* __restrict__ Plo)
{
    const float inv_scale = 0.0883883476483184f;  // 1/sqrt(128)
    const float* row = S + (long long)blockIdx.x * SEQ;
    int tid = threadIdx.x;

    float4 a = ((const float4*)row)[tid];
    float4 b = ((const float4*)row)[tid + 256];
    a.x*=inv_scale; a.y*=inv_scale; a.z*=inv_scale; a.w*=inv_scale;
    b.x*=inv_scale; b.y*=inv_scale; b.z*=inv_scale; b.w*=inv_scale;

    float m = fmaxf(fmaxf(fmaxf(a.x,a.y), fmaxf(a.z,a.w)),
                    fmaxf(fmaxf(b.x,b.y), fmaxf(b.z,b.w)));
    m = block_max(m);
    a.x=expf(a.x-m); a.y=expf(a.y-m); a.z=expf(a.z-m); a.w=expf(a.w-m);
    b.x=expf(b.x-m); b.y=expf(b.y-m); b.z=expf(b.z-m); b.w=expf(b.w-m);
    float s = a.x+a.y+a.z+a.w + b.x+b.y+b.z+b.w;
    s = block_sum(s);
    float inv = 1.0f / s;
    a.x*=inv; a.y*=inv; a.z*=inv; a.w*=inv;
    b.x*=inv; b.y*=inv; b.z*=inv; b.w*=inv;

    long long base = (long long)blockIdx.x * SEQ;
    bf16 h0,l0,h1,l1,h2,l2,h3,l3;
    split1(a.x,h0,l0); split1(a.y,h1,l1); split1(a.z,h2,l2); split1(a.w,h3,l3);
    ((uint2*)(Phi + base))[tid] = make_uint2(pack2(h0,h1), pack2(h2,h3));
    ((uint2*)(Plo + base))[tid] = make_uint2(pack2(l0,l1), pack2(l2,l3));
    split1(b.x,h0,l0); split1(b.y,h1,l1); split1(b.z,h2,l2); split1(b.w,h3,l3);
    ((uint2*)(Phi + base))[tid + 256] = make_uint2(pack2(h0,h1), pack2(h2,h3));
    ((uint2*)(Plo + base))[tid + 256] = make_uint2(pack2(l0,l1), pack2(l2,l3));
}

// ---------------------------------------------------------------------------
// LayerNorm D=1024; optional split emission.
// ---------------------------------------------------------------------------
template<bool SPLIT>
__global__ __launch_bounds__(256) void layernorm_kernel(
    const float* __restrict__ X, const float* __restrict__ g,
    const float* __restrict__ b, float* __restrict__ Y,
    bf16* __restrict__ Yhi, bf16* __restrict__ Ylo)
{
    const float* x = X + (long long)blockIdx.x * D_MODEL;
    int tid = threadIdx.x;
    float4 v = ((const float4*)x)[tid];
    float s = v.x + v.y + v.z + v.w;
    s = block_sum(s);
    float mean = s * (1.0f / D_MODEL);
    float dx=v.x-mean, dy=v.y-mean, dz=v.z-mean, dw=v.w-mean;
    float ss = dx*dx + dy*dy + dz*dz + dw*dw;
    ss = block_sum(ss);
    float rstd = rsqrtf(ss * (1.0f / D_MODEL) + 1e-5f);
    float4 gg = ((const float4*)g)[tid];
    float4 bb = ((const float4*)b)[tid];
    float4 o;
    o.x = dx*rstd*gg.x + bb.x;
    o.y = dy*rstd*gg.y + bb.y;
    o.z = dz*rstd*gg.z + bb.z;
    o.w = dw*rstd*gg.w + bb.w;
    long long base = (long long)blockIdx.x * D_MODEL;
    ((float4*)(Y + base))[tid] = o;
    if (SPLIT) {
        bf16 h0,l0,h1,l1,h2,l2,h3,l3;
        split1(o.x,h0,l0); split1(o.y,h1,l1); split1(o.z,h2,l2); split1(o.w,h3,l3);
        ((uint2*)(Yhi + base))[tid] = make_uint2(pack2(h0,h1), pack2(h2,h3));
        ((uint2*)(Ylo + base))[tid] = make_uint2(pack2(l0,l1), pack2(l2,l3));
    }
}

// ---------------------------------------------------------------------------
// Launch
// ---------------------------------------------------------------------------
extern "C" void kernel_launch(void* const* d_in, const int* in_sizes, int n_in,
                              void* d_out, int out_size)
{
    const float* x     = (const float*)d_in[0];
    const float* wq    = (const float*)d_in[1];
    const float* bq    = (const float*)d_in[2];
    const float* wk    = (const float*)d_in[3];
    const float* bk    = (const float*)d_in[4];
    const float* wv    = (const float*)d_in[5];
    const float* bv    = (const float*)d_in[6];
    const float* wo    = (const float*)d_in[7];
    const float* bo    = (const float*)d_in[8];
    const float* w1    = (const float*)d_in[9];
    const float* b1    = (const float*)d_in[10];
    const float* w2    = (const float*)d_in[11];
    const float* b2    = (const float*)d_in[12];
    const float* g1    = (const float*)d_in[13];
    const float* beta1 = (const float*)d_in[14];
    const float* g2    = (const float*)d_in[15];
    const float* beta2 = (const float*)d_in[16];
    float* out = (float*)d_out;

    #define SYM(p, s) void* p##_; cudaGetSymbolAddress(&p##_, s);
    SYM(xh, g_x_hi)  SYM(xl, g_x_lo)
    SYM(wqh, g_wqT_hi) SYM(wql, g_wqT_lo)
    SYM(wkh, g_wkT_hi) SYM(wkl, g_wkT_lo)
    SYM(wvh, g_wvT_hi) SYM(wvl, g_wvT_lo)
    SYM(woh, g_woT_hi) SYM(wol, g_woT_lo)
    SYM(w1h, g_w1T_hi) SYM(w1l, g_w1T_lo)
    SYM(w2h, g_w2T_hi) SYM(w2l, g_w2T_lo)
    SYM(qh, g_q_hi)  SYM(ql, g_q_lo)
    SYM(kh, g_k_hi)  SYM(kl, g_k_lo)
    SYM(vv, g_v)     SYM(vth, g_vT_hi) SYM(vtl, g_vT_lo)
    SYM(sc, g_s)     SYM(ph, g_p_hi)   SYM(pl, g_p_lo)
    SYM(ch, g_ctx_hi) SYM(cl, g_ctx_lo)
    SYM(x1, g_x1)    SYM(y1, g_y1)  SYM(y1h, g_y1_hi) SYM(y1l, g_y1_lo)
    SYM(hh, g_h_hi)  SYM(hl, g_h_lo)
    SYM(x2, g_x2)
    #undef SYM

    cudaFuncSetAttribute(gemm_nt<1,0,0,0>, cudaFuncAttributeMaxDynamicSharedMemorySize, SMEM_TOTAL);
    cudaFuncSetAttribute(gemm_nt<0,1,0,0>, cudaFuncAttributeMaxDynamicSharedMemorySize, SMEM_TOTAL);
    cudaFuncSetAttribute(gemm_nt<0,1,1,0>, cudaFuncAttributeMaxDynamicSharedMemorySize, SMEM_TOTAL);
    cudaFuncSetAttribute(gemm_nt<1,0,0,1>, cudaFuncAttributeMaxDynamicSharedMemorySize, SMEM_TOTAL);

    dim3 blk(256);

    // 0. split x
    split_kernel<<<M_TOT * D_MODEL / 4 / 256, blk>>>(x, (bf16*)xh_, (bf16*)xl_, M_TOT * D_MODEL / 4);

    // 1. transpose-split the four DxD weights in one launch
    transpose_split4_kernel<<<dim3(D_MODEL/32, D_MODEL/32, 4), blk>>>(
        wq, wk, wv, wo,
        (bf16*)wqh_, (bf16*)wql_, (bf16*)wkh_, (bf16*)wkl_,
        (bf16*)wvh_, (bf16*)wvl_, (bf16*)woh_, (bf16*)wol_);

    // 2-3. w1, w2 transposes
    transpose_split_kernel<<<dim3(FF_DIM/32, D_MODEL/32, 1), blk>>>(w1, (bf16*)w1h_, (bf16*)w1l_, D_MODEL, FF_DIM, 0, 0);
    transpose_split_kernel<<<dim3(D_MODEL/32, FF_DIM/32, 1), blk>>>(w2, (bf16*)w2h_, (bf16*)w2l_, FF_DIM, D_MODEL, 0, 0);

    // 4-6. q, k (split-out), v (fp32)
    {
        dim3 g(D_MODEL/BN, M_TOT/BM, 1);
        gemm_nt<0,1,0,0><<<g, blk, SMEM_TOTAL>>>((bf16*)xh_, (bf16*)xl_, (bf16*)wqh_, (bf16*)wql_,
            bq, nullptr, nullptr, (bf16*)qh_, (bf16*)ql_, M_TOT, D_MODEL, D_MODEL, 0, 0, 0);
        gemm_nt<0,1,0,0><<<g, blk, SMEM_TOTAL>>>((bf16*)xh_, (bf16*)xl_, (bf16*)wkh_, (bf16*)wkl_,
            bk, nullptr, nullptr, (bf16*)kh_, (bf16*)kl_, M_TOT, D_MODEL, D_MODEL, 0, 0, 0);
        gemm_nt<1,0,0,0><<<g, blk, SMEM_TOTAL>>>((bf16*)xh_, (bf16*)xl_, (bf16*)wvh_, (bf16*)wvl_,
            bv, nullptr, (float*)vv_, nullptr, nullptr, M_TOT, D_MODEL, D_MODEL, 0, 0, 0);
    }

    // 7. vT per batch: [2048,1024] -> [1024,2048]
    transpose_split_kernel<<<dim3(D_MODEL/32, SEQ/32, BATCH), blk>>>((float*)vv_,
        (bf16*)vth_, (bf16*)vtl_, SEQ, D_MODEL, (long long)SEQ*D_MODEL, (long long)SEQ*D_MODEL);

    // 8. scores = q @ k^T (fp32 out)
    gemm_nt<1,0,0,0><<<dim3(SEQ/BN, SEQ/BM, BATCH), blk, SMEM_TOTAL>>>(
        (bf16*)qh_, (bf16*)ql_, (bf16*)kh_, (bf16*)kl_, nullptr, nullptr,
        (float*)sc_, nullptr, nullptr, SEQ, SEQ, D_MODEL,
        (long long)SEQ*D_MODEL, (long long)SEQ*D_MODEL, (long long)SEQ*SEQ);

    // 9. softmax + split
    softmax_split_kernel<<<BATCH*SEQ, blk>>>((float*)sc_, (bf16*)ph_, (bf16*)pl_);

    // 10. ctx = attn @ vT^T (split out)
    gemm_nt<0,1,0,0><<<dim3(D_MODEL/BN, SEQ/BM, BATCH), blk, SMEM_TOTAL>>>(
        (bf16*)ph_, (bf16*)pl_, (bf16*)vth_, (bf16*)vtl_, nullptr, nullptr,
        nullptr, (bf16*)ch_, (bf16*)cl_, SEQ, D_MODEL, SEQ,
        (long long)SEQ*SEQ, (long long)SEQ*D_MODEL, (long long)SEQ*D_MODEL);

    // 11. x1 = x + ctx @ wo^T + bo
    gemm_nt<1,0,0,1><<<dim3(D_MODEL/BN, M_TOT/BM, 1), blk, SMEM_TOTAL>>>(
        (bf16*)ch_, (bf16*)cl_, (bf16*)woh_, (bf16*)wol_, bo, x,
        (float*)x1_, nullptr, nullptr, M_TOT, D_MODEL, D_MODEL, 0, 0, 0);

    // 12. y1 = LN1(x1) + split
    layernorm_kernel<true><<<M_TOT, blk>>>((float*)x1_, g1, beta1, (float*)y1_, (bf16*)y1h_, (bf16*)y1l_);

    // 13. h = relu(y1 @ w1^T + b1) (split out)
    gemm_nt<0,1,1,0><<<dim3(FF_DIM/BN, M_TOT/BM, 1), blk, SMEM_TOTAL>>>(
        (bf16*)y1h_, (bf16*)y1l_, (bf16*)w1h_, (bf16*)w1l_, b1, nullptr,
        nullptr, (bf16*)hh_, (bf16*)hl_, M_TOT, FF_DIM, D_MODEL, 0, 0, 0);

    // 14. x2 = y1 + h @ w2^T + b2
    gemm_nt<1,0,0,1><<<dim3(D_MODEL/BN, M_TOT/BM, 1), blk, SMEM_TOTAL>>>(
        (bf16*)hh_, (bf16*)hl_, (bf16*)w2h_, (bf16*)w2l_, b2, (float*)y1_,
        (float*)x2_, nullptr, nullptr, M_TOT, D_MODEL, FF_DIM, 0, 0, 0);

    // 15. out = LN2(x2)
    layernorm_kernel<false><<<M_TOT, blk>>>((float*)x2_, g2, beta2, out, nullptr, nullptr);
}

// round 6
// speedup vs baseline: 2.7135x; 1.0614x over previous
#include <cuda_runtime.h>
#include <cuda_bf16.h>
#include <math.h>
#include <stdint.h>

// ---------------------------------------------------------------------------
// SmallTransformerBlock via mma.sync bf16x3 split GEMMs (sm_103 baseline PTX).
// R6: BN=64 CTA tile (warp tile 32x32) -> acc 32 regs, no spills at 2 CTAs/SM.
// SW128-swizzled SMEM rows (hi chunks 0-3, lo chunks 4-7), 3-stage cp.async.
// Launch order puts GEMM q at stream index 2 so ncu (-s 5) captures it.
// ---------------------------------------------------------------------------

#define D_MODEL 1024
#define FF_DIM  4096
#define BATCH   4
#define SEQ     2048
#define M_TOT   (BATCH * SEQ)          // 8192

#define BM 128
#define BN 64
#define BK 32
#define STAGES 3
#define ABUF_BYTES (128 * 128)                // A: 128 rows x 128B
#define BBUF_BYTES (64 * 128)                 // B: 64 rows x 128B
#define STAGE_BYTES (ABUF_BYTES + BBUF_BYTES) // 24576
#define SMEM_TOTAL  (STAGES * STAGE_BYTES)    // 73728

typedef __nv_bfloat16 bf16;

// -------------------------- scratch (device globals) -----------------------
__device__ bf16  g_x_hi [M_TOT * D_MODEL];
__device__ bf16  g_x_lo [M_TOT * D_MODEL];
__device__ bf16  g_wqT_hi[D_MODEL * D_MODEL];
__device__ bf16  g_wqT_lo[D_MODEL * D_MODEL];
__device__ bf16  g_wkT_hi[D_MODEL * D_MODEL];
__device__ bf16  g_wkT_lo[D_MODEL * D_MODEL];
__device__ bf16  g_wvT_hi[D_MODEL * D_MODEL];
__device__ bf16  g_wvT_lo[D_MODEL * D_MODEL];
__device__ bf16  g_woT_hi[D_MODEL * D_MODEL];
__device__ bf16  g_woT_lo[D_MODEL * D_MODEL];
__device__ bf16  g_w1T_hi[FF_DIM * D_MODEL];
__device__ bf16  g_w1T_lo[FF_DIM * D_MODEL];
__device__ bf16  g_w2T_hi[D_MODEL * FF_DIM];
__device__ bf16  g_w2T_lo[D_MODEL * FF_DIM];
__device__ bf16  g_q_hi [M_TOT * D_MODEL];
__device__ bf16  g_q_lo [M_TOT * D_MODEL];
__device__ bf16  g_k_hi [M_TOT * D_MODEL];
__device__ bf16  g_k_lo [M_TOT * D_MODEL];
__device__ float g_v    [M_TOT * D_MODEL];
__device__ bf16  g_vT_hi[M_TOT * D_MODEL];     // [B][D,T]
__device__ bf16  g_vT_lo[M_TOT * D_MODEL];
__device__ float g_s    [BATCH * SEQ * SEQ];
__device__ bf16  g_p_hi [BATCH * SEQ * SEQ];
__device__ bf16  g_p_lo [BATCH * SEQ * SEQ];
__device__ bf16  g_ctx_hi[M_TOT * D_MODEL];
__device__ bf16  g_ctx_lo[M_TOT * D_MODEL];
__device__ float g_x1   [M_TOT * D_MODEL];
__device__ float g_y1   [M_TOT * D_MODEL];
__device__ bf16  g_y1_hi[M_TOT * D_MODEL];
__device__ bf16  g_y1_lo[M_TOT * D_MODEL];
__device__ bf16  g_h_hi [M_TOT * FF_DIM];
__device__ bf16  g_h_lo [M_TOT * FF_DIM];
__device__ float g_x2   [M_TOT * D_MODEL];

// ------------------------------- PTX helpers -------------------------------
__device__ __forceinline__ uint32_t smem_u32(const void* p) {
    uint32_t a;
    asm("{ .reg .u64 t; cvta.to.shared.u64 t, %1; cvt.u32.u64 %0, t; }"
        : "=r"(a) : "l"(p));
    return a;
}
__device__ __forceinline__ void cp16(uint32_t dst, const void* src) {
    asm volatile("cp.async.cg.shared.global [%0], [%1], 16;\n" :: "r"(dst), "l"(src));
}
__device__ __forceinline__ void cp_commit() {
    asm volatile("cp.async.commit_group;\n" ::: "memory");
}
template<int N> __device__ __forceinline__ void cp_wait() {
    asm volatile("cp.async.wait_group %0;\n" :: "n"(N) : "memory");
}
__device__ __forceinline__ void ldsm4(uint32_t& r0, uint32_t& r1, uint32_t& r2,
                                      uint32_t& r3, uint32_t addr) {
    asm volatile("ldmatrix.sync.aligned.m8n8.x4.shared.b16 {%0,%1,%2,%3}, [%4];\n"
                 : "=r"(r0), "=r"(r1), "=r"(r2), "=r"(r3) : "r"(addr));
}
__device__ __forceinline__ void mma16816(float* d, const uint32_t* a, const uint32_t* b) {
    asm volatile(
        "mma.sync.aligned.m16n8k16.row.col.f32.bf16.bf16.f32 "
        "{%0,%1,%2,%3}, {%4,%5,%6,%7}, {%8,%9}, {%0,%1,%2,%3};\n"
        : "+f"(d[0]), "+f"(d[1]), "+f"(d[2]), "+f"(d[3])
        : "r"(a[0]), "r"(a[1]), "r"(a[2]), "r"(a[3]), "r"(b[0]), "r"(b[1]));
}
__device__ __forceinline__ void split1(float v, bf16& h, bf16& l) {
    h = __float2bfloat16(v);
    l = __float2bfloat16(v - __bfloat162float(h));
}
__device__ __forceinline__ uint32_t pack2(bf16 a, bf16 b) {
    return ((uint32_t)__bfloat16_as_ushort(b) << 16) | __bfloat16_as_ushort(a);
}

// ---------------------------------------------------------------------------
// GEMM NT bf16x3: C[M,N] = (Ah+Al) @ (Bh+Bl)^T (+bias)(relu)(+res)
// 128x64x32 tile, 8 warps (warp tile 32x32), 3-stage cp.async, 2 CTAs/SM.
// ---------------------------------------------------------------------------
template<bool F32OUT, bool SPLITOUT, bool RELU, bool HASRES>
__global__ __launch_bounds__(256, 2) void gemm_nt(
    const bf16* __restrict__ Ahi, const bf16* __restrict__ Alo,
    const bf16* __restrict__ Bhi, const bf16* __restrict__ Blo,
    const float* __restrict__ bias, const float* __restrict__ Res,
    float* __restrict__ Cf, bf16* __restrict__ Chi, bf16* __restrict__ Clo,
    int M, int N, int K, long long aS, long long bS, long long cS)
{
    extern __shared__ char smraw[];
    const uint32_t smb = smem_u32(smraw);
    const int tid  = threadIdx.x;
    const int wid  = tid >> 5;
    const int lane = tid & 31;
    const int wm = wid & 3;            // m offset wm*32
    const int wn = wid >> 2;           // n offset wn*32
    const int quad = lane >> 3, lrow = lane & 7;
    const int bz = blockIdx.z;
    const int bm = blockIdx.y * BM;
    const int bn = blockIdx.x * BN;

    const bf16* Ah = Ahi + (long long)bz * aS;
    const bf16* Al = Alo + (long long)bz * aS;
    const bf16* Bh = Bhi + (long long)bz * bS;
    const bf16* Bl = Blo + (long long)bz * bS;

    float acc[2][4][4];
    #pragma unroll
    for (int i = 0; i < 2; i++)
        #pragma unroll
        for (int j = 0; j < 4; j++)
            #pragma unroll
            for (int c = 0; c < 4; c++) acc[i][j][c] = 0.0f;

    const int T = K / BK;

    // per-thread constant load mapping: chunk index fixed = tid&7
    const int lc   = tid & 7;
    const bool lhi = (lc < 4);
    const int lk   = (lhi ? lc : lc - 4) * 8;

    auto load_stage = [&](int kt, int s) {
        const uint32_t st = smb + s * STAGE_BYTES;
        const int k0 = kt * BK;
        #pragma unroll
        for (int i = 0; i < 6; i++) {          // 1536 chunks / 256 threads
            int id = tid + i * 256;            // 0..1535
            bool isB = (id >= 1024);
            int row = isB ? ((id - 1024) >> 3) : (id >> 3);
            uint32_t dst = st + (isB ? ABUF_BYTES : 0u)
                         + (uint32_t)(row * 128 + ((lc ^ (row & 7)) * 16));
            const bf16* base = isB ? (lhi ? Bh : Bl) : (lhi ? Ah : Al);
            long long g = (long long)((isB ? bn : bm) + row) * K + k0 + lk;
            cp16(dst, base + g);
        }
    };

    auto compute_stage = [&](int s) {
        const uint32_t stA = smb + s * STAGE_BYTES;
        const uint32_t stB = stA + ABUF_BYTES;
        #pragma unroll
        for (int ks = 0; ks < 2; ks++) {
            const int ch = ks * 2 + (quad >> 1);   // hi chunk 0-3
            uint32_t ah[2][4], al[2][4];
            #pragma unroll
            for (int fm = 0; fm < 2; fm++) {
                int r = wm * 32 + fm * 16 + (quad & 1) * 8 + lrow;
                uint32_t a_hi = stA + (uint32_t)(r * 128 + ((ch ^ (r & 7)) * 16));
                uint32_t a_lo = stA + (uint32_t)(r * 128 + (((ch + 4) ^ (r & 7)) * 16));
                ldsm4(ah[fm][0], ah[fm][1], ah[fm][2], ah[fm][3], a_hi);
                ldsm4(al[fm][0], al[fm][1], al[fm][2], al[fm][3], a_lo);
            }
            uint32_t bh[4][2], bl[4][2];
            #pragma unroll
            for (int f2 = 0; f2 < 2; f2++) {
                int r = wn * 32 + f2 * 16 + (quad & 1) * 8 + lrow;
                uint32_t b_hi = stB + (uint32_t)(r * 128 + ((ch ^ (r & 7)) * 16));
                uint32_t b_lo = stB + (uint32_t)(r * 128 + (((ch + 4) ^ (r & 7)) * 16));
                uint32_t t0, t1, t2, t3;
                ldsm4(t0, t1, t2, t3, b_hi);
                bh[2*f2][0] = t0; bh[2*f2][1] = t2;
                bh[2*f2+1][0] = t1; bh[2*f2+1][1] = t3;
                ldsm4(t0, t1, t2, t3, b_lo);
                bl[2*f2][0] = t0; bl[2*f2][1] = t2;
                bl[2*f2+1][0] = t1; bl[2*f2+1][1] = t3;
            }
            #pragma unroll
            for (int fm = 0; fm < 2; fm++)
                #pragma unroll
                for (int fn = 0; fn < 4; fn++) {
                    float* d = acc[fm][fn];
                    mma16816(d, ah[fm], bh[fn]);
                    mma16816(d, ah[fm], bl[fn]);
                    mma16816(d, al[fm], bh[fn]);
                }
        }
    };

    load_stage(0, 0); cp_commit();
    load_stage(1, 1); cp_commit();

    for (int t = 0; t < T; t++) {
        if (t < T - 1) cp_wait<1>(); else cp_wait<0>();
        __syncthreads();
        if (t + 2 < T) { load_stage(t + 2, (t + 2) % STAGES); cp_commit(); }
        compute_stage(t % STAGES);
    }

    // ---------------- epilogue ----------------
    const int groupID = lane >> 2, tIdx = lane & 3;
    #pragma unroll
    for (int fm = 0; fm < 2; fm++) {
        #pragma unroll
        for (int half = 0; half < 2; half++) {
            int row = bm + wm * 32 + fm * 16 + half * 8 + groupID;
            long long rbase = (long long)bz * cS + (long long)row * N;
            #pragma unroll
            for (int fn = 0; fn < 4; fn++) {
                int col = bn + wn * 32 + fn * 8 + tIdx * 2;
                float v0 = acc[fm][fn][half * 2 + 0];
                float v1 = acc[fm][fn][half * 2 + 1];
                if (bias) { v0 += __ldg(bias + col); v1 += __ldg(bias + col + 1); }
                if (RELU) { v0 = fmaxf(v0, 0.0f); v1 = fmaxf(v1, 0.0f); }
                if (HASRES) {
                    float2 rv = *(const float2*)(Res + rbase + col);
                    v0 += rv.x; v1 += rv.y;
                }
                if (F32OUT)
                    *(float2*)(Cf + rbase + col) = make_float2(v0, v1);
                if (SPLITOUT) {
                    bf16 h0, l0, h1, l1;
                    split1(v0, h0, l0); split1(v1, h1, l1);
                    *(uint32_t*)(Chi + rbase + col) = pack2(h0, h1);
                    *(uint32_t*)(Clo + rbase + col) = pack2(l0, l1);
                }
            }
        }
    }
}

// ---------------------------------------------------------------------------
// Elementwise split: fp32 -> (hi, lo) bf16
// ---------------------------------------------------------------------------
__global__ __launch_bounds__(256) void split_kernel(
    const float* __restrict__ src, bf16* __restrict__ hi, bf16* __restrict__ lo, int n4)
{
    int i = blockIdx.x * 256 + threadIdx.x;
    if (i >= n4) return;
    float4 v = ((const float4*)src)[i];
    bf16 h0,l0,h1,l1,h2,l2,h3,l3;
    split1(v.x,h0,l0); split1(v.y,h1,l1); split1(v.z,h2,l2); split1(v.w,h3,l3);
    ((uint2*)hi)[i] = make_uint2(pack2(h0,h1), pack2(h2,h3));
    ((uint2*)lo)[i] = make_uint2(pack2(l0,l1), pack2(l2,l3));
}

// ---------------------------------------------------------------------------
// Transpose-split: src [R,C] fp32 -> dst [C,R] (hi, lo) bf16.
// ---------------------------------------------------------------------------
__global__ __launch_bounds__(256) void transpose_split_kernel(
    const float* __restrict__ src, bf16* __restrict__ hiT, bf16* __restrict__ loT,
    int R, int C, long long sS, long long dS)
{
    __shared__ float tile[32][33];
    const float* S = src + (long long)blockIdx.z * sS;
    int c0 = blockIdx.x * 32, r0 = blockIdx.y * 32;
    int tx = threadIdx.x & 31, ty = threadIdx.x >> 5;   // 32 x 8
    #pragma unroll
    for (int i = 0; i < 32; i += 8)
        tile[ty + i][tx] = S[(long long)(r0 + ty + i) * C + c0 + tx];
    __syncthreads();
    #pragma unroll
    for (int i = 0; i < 32; i += 8) {
        float v = tile[tx][ty + i];
        bf16 h, l; split1(v, h, l);
        long long o = (long long)blockIdx.z * dS + (long long)(c0 + ty + i) * R + r0 + tx;
        hiT[o] = h; loT[o] = l;
    }
}

// Batched version for the four 1024x1024 weights: z picks the weight.
__global__ __launch_bounds__(256) void transpose_split4_kernel(
    const float* __restrict__ s0, const float* __restrict__ s1,
    const float* __restrict__ s2, const float* __restrict__ s3,
    bf16* __restrict__ h0, bf16* __restrict__ l0,
    bf16* __restrict__ h1, bf16* __restrict__ l1,
    bf16* __restrict__ h2, bf16* __restrict__ l2,
    bf16* __restrict__ h3, bf16* __restrict__ l3)
{
    __shared__ float tile[32][33];
    const int z = blockIdx.z;
    const float* S = (z == 0) ? s0 : (z == 1) ? s1 : (z == 2) ? s2 : s3;
    bf16* H = (z == 0) ? h0 : (z == 1) ? h1 : (z == 2) ? h2 : h3;
    bf16* L = (z == 0) ? l0 : (z == 1) ? l1 : (z == 2) ? l2 : l3;
    int c0 = blockIdx.x * 32, r0 = blockIdx.y * 32;
    int tx = threadIdx.x & 31, ty = threadIdx.x >> 5;
    #pragma unroll
    for (int i = 0; i < 32; i += 8)
        tile[ty + i][tx] = S[(long long)(r0 + ty + i) * D_MODEL + c0 + tx];
    __syncthreads();
    #pragma unroll
    for (int i = 0; i < 32; i += 8) {
        float v = tile[tx][ty + i];
        bf16 h, l; split1(v, h, l);
        long long o = (long long)(c0 + ty + i) * D_MODEL + r0 + tx;
        H[o] = h; L[o] = l;
    }
}

// ------------------------------- reductions --------------------------------
__device__ __forceinline__ float block_sum(float v) {
    __shared__ float sh[8];
    int lane = threadIdx.x & 31, w = threadIdx.x >> 5;
    #pragma unroll
    for (int o = 16; o > 0; o >>= 1) v += __shfl_xor_sync(0xffffffffu, v, o);
    if (lane == 0) sh[w] = v;
    __syncthreads();
    if (w == 0) {
        float t = (lane < 8) ? sh[lane] : 0.0f;
        #pragma unroll
        for (int o = 4; o > 0; o >>= 1) t += __shfl_xor_sync(0xffffffffu, t, o);
        if (lane == 0) sh[0] = t;
    }
    __syncthreads();
    float r = sh[0];
    __syncthreads();
    return r;
}
__device__ __forceinline__ float block_max(float v) {
    __shared__ float sh[8];
    int lane = threadIdx.x & 31, w = threadIdx.x >> 5;
    #pragma unroll
    for (int o = 16; o > 0; o >>= 1) v = fmaxf(v, __shfl_xor_sync(0xffffffffu, v, o));
    if (lane == 0) sh[w] = v;
    __syncthreads();
    if (w == 0) {
        float t = (lane < 8) ? sh[lane] : -3.4e38f;
        #pragma unroll
        for (int o = 4; o > 0; o >>= 1) t = fmaxf(t, __shfl_xor_sync(0xffffffffu, t, o));
        if (lane == 0) sh[0] = t;
    }
    __syncthreads();
    float r = sh[0];
    __syncthreads();
    return r;
}

// ---------------------------------------------------------------------------
// Softmax over SEQ=2048 with fused 1/scale; outputs pre-split hi/lo bf16.
// ---------------------------------------------------------------------------
__global__ __launch_bounds__(256) void softmax_split_kernel(
    const float* __restrict__ S, bf16* __restrict__ Phi, bf16* __restrict__ Plo)
{
    const float inv_scale = 0.0883883476483184f;  // 1/sqrt(128)
    const float* row = S + (long long)blockIdx.x * SEQ;
    int tid = threadIdx.x;

    float4 a = ((const float4*)row)[tid];
    float4 b = ((const float4*)row)[tid + 256];
    a.x*=inv_scale; a.y*=inv_scale; a.z*=inv_scale; a.w*=inv_scale;
    b.x*=inv_scale; b.y*=inv_scale; b.z*=inv_scale; b.w*=inv_scale;

    float m = fmaxf(fmaxf(fmaxf(a.x,a.y), fmaxf(a.z,a.w)),
                    fmaxf(fmaxf(b.x,b.y), fmaxf(b.z,b.w)));
    m = block_max(m);
    a.x=expf(a.x-m); a.y=expf(a.y-m); a.z=expf(a.z-m); a.w=expf(a.w-m);
    b.x=expf(b.x-m); b.y=expf(b.y-m); b.z=expf(b.z-m); b.w=expf(b.w-m);
    float s = a.x+a.y+a.z+a.w + b.x+b.y+b.z+b.w;
    s = block_sum(s);
    float inv = 1.0f / s;
    a.x*=inv; a.y*=inv; a.z*=inv; a.w*=inv;
    b.x*=inv; b.y*=inv; b.z*=inv; b.w*=inv;

    long long base = (long long)blockIdx.x * SEQ;
    bf16 h0,l0,h1,l1,h2,l2,h3,l3;
    split1(a.x,h0,l0); split1(a.y,h1,l1); split1(a.z,h2,l2); split1(a.w,h3,l3);
    ((uint2*)(Phi + base))[tid] = make_uint2(pack2(h0,h1), pack2(h2,h3));
    ((uint2*)(Plo + base))[tid] = make_uint2(pack2(l0,l1), pack2(l2,l3));
    split1(b.x,h0,l0); split1(b.y,h1,l1); split1(b.z,h2,l2); split1(b.w,h3,l3);
    ((uint2*)(Phi + base))[tid + 256] = make_uint2(pack2(h0,h1), pack2(h2,h3));
    ((uint2*)(Plo + base))[tid + 256] = make_uint2(pack2(l0,l1), pack2(l2,l3));
}

// ---------------------------------------------------------------------------
// LayerNorm D=1024; optional split emission.
// ---------------------------------------------------------------------------
template<bool SPLIT>
__global__ __launch_bounds__(256) void layernorm_kernel(
    const float* __restrict__ X, const float* __restrict__ g,
    const float* __restrict__ b, float* __restrict__ Y,
    bf16* __restrict__ Yhi, bf16* __restrict__ Ylo)
{
    const float* x = X + (long long)blockIdx.x * D_MODEL;
    int tid = threadIdx.x;
    float4 v = ((const float4*)x)[tid];
    float s = v.x + v.y + v.z + v.w;
    s = block_sum(s);
    float mean = s * (1.0f / D_MODEL);
    float dx=v.x-mean, dy=v.y-mean, dz=v.z-mean, dw=v.w-mean;
    float ss = dx*dx + dy*dy + dz*dz + dw*dw;
    ss = block_sum(ss);
    float rstd = rsqrtf(ss * (1.0f / D_MODEL) + 1e-5f);
    float4 gg = ((const float4*)g)[tid];
    float4 bb = ((const float4*)b)[tid];
    float4 o;
    o.x = dx*rstd*gg.x + bb.x;
    o.y = dy*rstd*gg.y + bb.y;
    o.z = dz*rstd*gg.z + bb.z;
    o.w = dw*rstd*gg.w + bb.w;
    long long base = (long long)blockIdx.x * D_MODEL;
    ((float4*)(Y + base))[tid] = o;
    if (SPLIT) {
        bf16 h0,l0,h1,l1,h2,l2,h3,l3;
        split1(o.x,h0,l0); split1(o.y,h1,l1); split1(o.z,h2,l2); split1(o.w,h3,l3);
        ((uint2*)(Yhi + base))[tid] = make_uint2(pack2(h0,h1), pack2(h2,h3));
        ((uint2*)(Ylo + base))[tid] = make_uint2(pack2(l0,l1), pack2(l2,l3));
    }
}

// ---------------------------------------------------------------------------
// Launch
// ---------------------------------------------------------------------------
extern "C" void kernel_launch(void* const* d_in, const int* in_sizes, int n_in,
                              void* d_out, int out_size)
{
    const float* x     = (const float*)d_in[0];
    const float* wq    = (const float*)d_in[1];
    const float* bq    = (const float*)d_in[2];
    const float* wk    = (const float*)d_in[3];
    const float* bk    = (const float*)d_in[4];
    const float* wv    = (const float*)d_in[5];
    const float* bv    = (const float*)d_in[6];
    const float* wo    = (const float*)d_in[7];
    const float* bo    = (const float*)d_in[8];
    const float* w1    = (const float*)d_in[9];
    const float* b1    = (const float*)d_in[10];
    const float* w2    = (const float*)d_in[11];
    const float* b2    = (const float*)d_in[12];
    const float* g1    = (const float*)d_in[13];
    const float* beta1 = (const float*)d_in[14];
    const float* g2    = (const float*)d_in[15];
    const float* beta2 = (const float*)d_in[16];
    float* out = (float*)d_out;

    #define SYM(p, s) void* p##_; cudaGetSymbolAddress(&p##_, s);
    SYM(xh, g_x_hi)  SYM(xl, g_x_lo)
    SYM(wqh, g_wqT_hi) SYM(wql, g_wqT_lo)
    SYM(wkh, g_wkT_hi) SYM(wkl, g_wkT_lo)
    SYM(wvh, g_wvT_hi) SYM(wvl, g_wvT_lo)
    SYM(woh, g_woT_hi) SYM(wol, g_woT_lo)
    SYM(w1h, g_w1T_hi) SYM(w1l, g_w1T_lo)
    SYM(w2h, g_w2T_hi) SYM(w2l, g_w2T_lo)
    SYM(qh, g_q_hi)  SYM(ql, g_q_lo)
    SYM(kh, g_k_hi)  SYM(kl, g_k_lo)
    SYM(vv, g_v)     SYM(vth, g_vT_hi) SYM(vtl, g_vT_lo)
    SYM(sc, g_s)     SYM(ph, g_p_hi)   SYM(pl, g_p_lo)
    SYM(ch, g_ctx_hi) SYM(cl, g_ctx_lo)
    SYM(x1, g_x1)    SYM(y1, g_y1)  SYM(y1h, g_y1_hi) SYM(y1l, g_y1_lo)
    SYM(hh, g_h_hi)  SYM(hl, g_h_lo)
    SYM(x2, g_x2)
    #undef SYM

    cudaFuncSetAttribute(gemm_nt<1,0,0,0>, cudaFuncAttributeMaxDynamicSharedMemorySize, SMEM_TOTAL);
    cudaFuncSetAttribute(gemm_nt<0,1,0,0>, cudaFuncAttributeMaxDynamicSharedMemorySize, SMEM_TOTAL);
    cudaFuncSetAttribute(gemm_nt<0,1,1,0>, cudaFuncAttributeMaxDynamicSharedMemorySize, SMEM_TOTAL);
    cudaFuncSetAttribute(gemm_nt<1,0,0,1>, cudaFuncAttributeMaxDynamicSharedMemorySize, SMEM_TOTAL);

    dim3 blk(256);

    // 0. split x
    split_kernel<<<M_TOT * D_MODEL / 4 / 256, blk>>>(x, (bf16*)xh_, (bf16*)xl_, M_TOT * D_MODEL / 4);

    // 1. transpose-split the four DxD weights in one launch
    transpose_split4_kernel<<<dim3(D_MODEL/32, D_MODEL/32, 4), blk>>>(
        wq, wk, wv, wo,
        (bf16*)wqh_, (bf16*)wql_, (bf16*)wkh_, (bf16*)wkl_,
        (bf16*)wvh_, (bf16*)wvl_, (bf16*)woh_, (bf16*)wol_);

    // 2-4. q, k (split-out), v (fp32)  [launch #2 = GEMM for ncu capture]
    {
        dim3 g(D_MODEL/BN, M_TOT/BM, 1);
        gemm_nt<0,1,0,0><<<g, blk, SMEM_TOTAL>>>((bf16*)xh_, (bf16*)xl_, (bf16*)wqh_, (bf16*)wql_,
            bq, nullptr, nullptr, (bf16*)qh_, (bf16*)ql_, M_TOT, D_MODEL, D_MODEL, 0, 0, 0);
        gemm_nt<0,1,0,0><<<g, blk, SMEM_TOTAL>>>((bf16*)xh_, (bf16*)xl_, (bf16*)wkh_, (bf16*)wkl_,
            bk, nullptr, nullptr, (bf16*)kh_, (bf16*)kl_, M_TOT, D_MODEL, D_MODEL, 0, 0, 0);
        gemm_nt<1,0,0,0><<<g, blk, SMEM_TOTAL>>>((bf16*)xh_, (bf16*)xl_, (bf16*)wvh_, (bf16*)wvl_,
            bv, nullptr, (float*)vv_, nullptr, nullptr, M_TOT, D_MODEL, D_MODEL, 0, 0, 0);
    }

    // 5-6. w1, w2 transposes (needed only from launch 11 onward)
    transpose_split_kernel<<<dim3(FF_DIM/32, D_MODEL/32, 1), blk>>>(w1, (bf16*)w1h_, (bf16*)w1l_, D_MODEL, FF_DIM, 0, 0);
    transpose_split_kernel<<<dim3(D_MODEL/32, FF_DIM/32, 1), blk>>>(w2, (bf16*)w2h_, (bf16*)w2l_, FF_DIM, D_MODEL, 0, 0);

    // 7. vT per batch: [2048,1024] -> [1024,2048]
    transpose_split_kernel<<<dim3(D_MODEL/32, SEQ/32, BATCH), blk>>>((float*)vv_,
        (bf16*)vth_, (bf16*)vtl_, SEQ, D_MODEL, (long long)SEQ*D_MODEL, (long long)SEQ*D_MODEL);

    // 8. scores = q @ k^T (fp32 out)
    gemm_nt<1,0,0,0><<<dim3(SEQ/BN, SEQ/BM, BATCH), blk, SMEM_TOTAL>>>(
        (bf16*)qh_, (bf16*)ql_, (bf16*)kh_, (bf16*)kl_, nullptr, nullptr,
        (float*)sc_, nullptr, nullptr, SEQ, SEQ, D_MODEL,
        (long long)SEQ*D_MODEL, (long long)SEQ*D_MODEL, (long long)SEQ*SEQ);

    // 9. softmax + split
    softmax_split_kernel<<<BATCH*SEQ, blk>>>((float*)sc_, (bf16*)ph_, (bf16*)pl_);

    // 10. ctx = attn @ vT^T (split out)
    gemm_nt<0,1,0,0><<<dim3(D_MODEL/BN, SEQ/BM, BATCH), blk, SMEM_TOTAL>>>(
        (bf16*)ph_, (bf16*)pl_, (bf16*)vth_, (bf16*)vtl_, nullptr, nullptr,
        nullptr, (bf16*)ch_, (bf16*)cl_, SEQ, D_MODEL, SEQ,
        (long long)SEQ*SEQ, (long long)SEQ*D_MODEL, (long long)SEQ*D_MODEL);

    // 11. x1 = x + ctx @ wo^T + bo
    gemm_nt<1,0,0,1><<<dim3(D_MODEL/BN, M_TOT/BM, 1), blk, SMEM_TOTAL>>>(
        (bf16*)ch_, (bf16*)cl_, (bf16*)woh_, (bf16*)wol_, bo, x,
        (float*)x1_, nullptr, nullptr, M_TOT, D_MODEL, D_MODEL, 0, 0, 0);

    // 12. y1 = LN1(x1) + split
    layernorm_kernel<true><<<M_TOT, blk>>>((float*)x1_, g1, beta1, (float*)y1_, (bf16*)y1h_, (bf16*)y1l_);

    // 13. h = relu(y1 @ w1^T + b1) (split out)
    gemm_nt<0,1,1,0><<<dim3(FF_DIM/BN, M_TOT/BM, 1), blk, SMEM_TOTAL>>>(
        (bf16*)y1h_, (bf16*)y1l_, (bf16*)w1h_, (bf16*)w1l_, b1, nullptr,
        nullptr, (bf16*)hh_, (bf16*)hl_, M_TOT, FF_DIM, D_MODEL, 0, 0, 0);

    // 14. x2 = y1 + h @ w2^T + b2
    gemm_nt<1,0,0,1><<<dim3(D_MODEL/BN, M_TOT/BM, 1), blk, SMEM_TOTAL>>>(
        (bf16*)hh_, (bf16*)hl_, (bf16*)w2h_, (bf16*)w2l_, b2, (float*)y1_,
        (float*)x2_, nullptr, nullptr, M_TOT, D_MODEL, FF_DIM, 0, 0, 0);

    // 15. out = LN2(x2)
    layernorm_kernel<false><<<M_TOT, blk>>>((float*)x2_, g2, beta2, out, nullptr, nullptr);
}

// round 8
// speedup vs baseline: 4.4344x; 1.6342x over previous
#include <cuda_runtime.h>
#include <cuda_fp16.h>
#include <math.h>
#include <stdint.h>

// ---------------------------------------------------------------------------
// SmallTransformerBlock via mma.sync fp16 asymmetric-split GEMMs (sm_103 PTX).
// C = A16 @ (Bh + Bl)^T : A quantized to fp16 (err 2^-12), B split hi+lo fp16.
// 2 MMA passes. BK=64, SW128-swizzled 128B rows, 3-stage cp.async, 2 CTAs/SM.
// R8 = R7 with the 6 call sites fixed to pass all 9 pointer args.
// ---------------------------------------------------------------------------

#define D_MODEL 1024
#define FF_DIM  4096
#define BATCH   4
#define SEQ     2048
#define M_TOT   (BATCH * SEQ)          // 8192

#define BM 128
#define BN 64
#define BK 64
#define STAGES 3
#define ABUF_BYTES (128 * 128)                 // A: 128 rows x 128B (64 fp16)
#define BBUF_BYTES (64 * 128)                  // Bh: 64 rows x 128B; Bl same
#define STAGE_BYTES (ABUF_BYTES + 2 * BBUF_BYTES)   // 32768
#define SMEM_TOTAL  (STAGES * STAGE_BYTES)          // 98304

typedef __half h16;

// -------------------------- scratch (device globals) -----------------------
__device__ h16   g_x16  [M_TOT * D_MODEL];
__device__ h16   g_wqT_h[D_MODEL * D_MODEL];
__device__ h16   g_wqT_l[D_MODEL * D_MODEL];
__device__ h16   g_wkT_h[D_MODEL * D_MODEL];
__device__ h16   g_wkT_l[D_MODEL * D_MODEL];
__device__ h16   g_wvT_h[D_MODEL * D_MODEL];
__device__ h16   g_wvT_l[D_MODEL * D_MODEL];
__device__ h16   g_woT_h[D_MODEL * D_MODEL];
__device__ h16   g_woT_l[D_MODEL * D_MODEL];
__device__ h16   g_w1T_h[FF_DIM * D_MODEL];
__device__ h16   g_w1T_l[FF_DIM * D_MODEL];
__device__ h16   g_w2T_h[D_MODEL * FF_DIM];
__device__ h16   g_w2T_l[D_MODEL * FF_DIM];
__device__ h16   g_q16  [M_TOT * D_MODEL];
__device__ h16   g_k_h  [M_TOT * D_MODEL];
__device__ h16   g_k_l  [M_TOT * D_MODEL];
__device__ float g_v    [M_TOT * D_MODEL];
__device__ h16   g_vT_h [M_TOT * D_MODEL];     // [B][D,T]
__device__ h16   g_vT_l [M_TOT * D_MODEL];
__device__ float g_s    [BATCH * SEQ * SEQ];
__device__ h16   g_p16  [BATCH * SEQ * SEQ];
__device__ h16   g_ctx16[M_TOT * D_MODEL];
__device__ float g_x1   [M_TOT * D_MODEL];
__device__ float g_y1   [M_TOT * D_MODEL];
__device__ h16   g_y116 [M_TOT * D_MODEL];
__device__ h16   g_h16a [M_TOT * FF_DIM];
__device__ float g_x2   [M_TOT * D_MODEL];

// ------------------------------- PTX helpers -------------------------------
__device__ __forceinline__ uint32_t smem_u32(const void* p) {
    uint32_t a;
    asm("{ .reg .u64 t; cvta.to.shared.u64 t, %1; cvt.u32.u64 %0, t; }"
        : "=r"(a) : "l"(p));
    return a;
}
__device__ __forceinline__ void cp16(uint32_t dst, const void* src) {
    asm volatile("cp.async.cg.shared.global [%0], [%1], 16;\n" :: "r"(dst), "l"(src));
}
__device__ __forceinline__ void cp_commit() {
    asm volatile("cp.async.commit_group;\n" ::: "memory");
}
template<int N> __device__ __forceinline__ void cp_wait() {
    asm volatile("cp.async.wait_group %0;\n" :: "n"(N) : "memory");
}
__device__ __forceinline__ void ldsm4(uint32_t& r0, uint32_t& r1, uint32_t& r2,
                                      uint32_t& r3, uint32_t addr) {
    asm volatile("ldmatrix.sync.aligned.m8n8.x4.shared.b16 {%0,%1,%2,%3}, [%4];\n"
                 : "=r"(r0), "=r"(r1), "=r"(r2), "=r"(r3) : "r"(addr));
}
__device__ __forceinline__ void mma16816(float* d, const uint32_t* a, const uint32_t* b) {
    asm volatile(
        "mma.sync.aligned.m16n8k16.row.col.f32.f16.f16.f32 "
        "{%0,%1,%2,%3}, {%4,%5,%6,%7}, {%8,%9}, {%0,%1,%2,%3};\n"
        : "+f"(d[0]), "+f"(d[1]), "+f"(d[2]), "+f"(d[3])
        : "r"(a[0]), "r"(a[1]), "r"(a[2]), "r"(a[3]), "r"(b[0]), "r"(b[1]));
}
__device__ __forceinline__ void split1h(float v, h16& h, h16& l) {
    h = __float2half_rn(v);
    l = __float2half_rn(v - __half2float(h));
}
__device__ __forceinline__ uint32_t pack2h(h16 a, h16 b) {
    return ((uint32_t)__half_as_ushort(b) << 16) | __half_as_ushort(a);
}

// ---------------------------------------------------------------------------
// GEMM NT fp16 2-pass: C[M,N] = A16 @ (Bh+Bl)^T (+bias)(relu)(+res)
// 128x64x64 tile, 8 warps (warp tile 32x32), 3-stage cp.async, 2 CTAs/SM.
// ---------------------------------------------------------------------------
template<bool F32OUT, bool HALFOUT, bool SPLITOUT, bool RELU, bool HASRES>
__global__ __launch_bounds__(256, 2) void gemm_nt(
    const h16* __restrict__ A16,
    const h16* __restrict__ Bhi, const h16* __restrict__ Blo,
    const float* __restrict__ bias, const float* __restrict__ Res,
    float* __restrict__ Cf, h16* __restrict__ Ch,
    h16* __restrict__ Chi, h16* __restrict__ Clo,
    int M, int N, int K, long long aS, long long bS, long long cS)
{
    extern __shared__ char smraw[];
    const uint32_t smb = smem_u32(smraw);
    const int tid  = threadIdx.x;
    const int wid  = tid >> 5;
    const int lane = tid & 31;
    const int wm = wid & 3;            // m offset wm*32
    const int wn = wid >> 2;           // n offset wn*32
    const int quad = lane >> 3, lrow = lane & 7;
    const int bz = blockIdx.z;
    const int bm = blockIdx.y * BM;
    const int bn = blockIdx.x * BN;

    const h16* Ap = A16 + (long long)bz * aS;
    const h16* Bh = Bhi + (long long)bz * bS;
    const h16* Bl = Blo + (long long)bz * bS;

    float acc[2][4][4];
    #pragma unroll
    for (int i = 0; i < 2; i++)
        #pragma unroll
        for (int j = 0; j < 4; j++)
            #pragma unroll
            for (int c = 0; c < 4; c++) acc[i][j][c] = 0.0f;

    const int T = K / BK;

    // per-thread constant chunk mapping
    const int lc = tid & 7;            // 16B chunk 0-7 within 128B row
    const int lk = lc * 8;             // k element offset within BK=64

    auto load_stage = [&](int kt, int s) {
        const uint32_t st = smb + s * STAGE_BYTES;
        const int k0 = kt * BK;
        // A: 1024 chunks
        #pragma unroll
        for (int i = 0; i < 4; i++) {
            int id = tid + i * 256;
            int row = id >> 3;
            uint32_t dst = st + (uint32_t)(row * 128 + ((lc ^ (row & 7)) * 16));
            cp16(dst, Ap + (long long)(bm + row) * K + k0 + lk);
        }
        // B: 1024 chunks (512 hi + 512 lo)
        #pragma unroll
        for (int i = 0; i < 4; i++) {
            int id = tid + i * 256;            // 0..1023
            int buf = id >> 9;                 // 0 = hi, 1 = lo
            int row = (id >> 3) & 63;
            uint32_t dst = st + ABUF_BYTES + (uint32_t)buf * BBUF_BYTES
                         + (uint32_t)(row * 128 + ((lc ^ (row & 7)) * 16));
            const h16* base = buf ? Bl : Bh;
            cp16(dst, base + (long long)(bn + row) * K + k0 + lk);
        }
    };

    auto compute_stage = [&](int s) {
        const uint32_t stA  = smb + s * STAGE_BYTES;
        const uint32_t stBh = stA + ABUF_BYTES;
        const uint32_t stBl = stBh + BBUF_BYTES;
        #pragma unroll
        for (int ks = 0; ks < 4; ks++) {
            const int ch = ks * 2 + (quad >> 1);   // chunk 0-7
            uint32_t ah[2][4];
            #pragma unroll
            for (int fm = 0; fm < 2; fm++) {
                int r = wm * 32 + fm * 16 + (quad & 1) * 8 + lrow;
                uint32_t a = stA + (uint32_t)(r * 128 + ((ch ^ (r & 7)) * 16));
                ldsm4(ah[fm][0], ah[fm][1], ah[fm][2], ah[fm][3], a);
            }
            uint32_t bh[4][2], bl[4][2];
            #pragma unroll
            for (int f2 = 0; f2 < 2; f2++) {
                int r = wn * 32 + f2 * 16 + (quad & 1) * 8 + lrow;
                uint32_t off = (uint32_t)(r * 128 + ((ch ^ (r & 7)) * 16));
                uint32_t t0, t1, t2, t3;
                ldsm4(t0, t1, t2, t3, stBh + off);
                bh[2*f2][0] = t0; bh[2*f2][1] = t2;
                bh[2*f2+1][0] = t1; bh[2*f2+1][1] = t3;
                ldsm4(t0, t1, t2, t3, stBl + off);
                bl[2*f2][0] = t0; bl[2*f2][1] = t2;
                bl[2*f2+1][0] = t1; bl[2*f2+1][1] = t3;
            }
            #pragma unroll
            for (int fm = 0; fm < 2; fm++)
                #pragma unroll
                for (int fn = 0; fn < 4; fn++) {
                    float* d = acc[fm][fn];
                    mma16816(d, ah[fm], bh[fn]);
                    mma16816(d, ah[fm], bl[fn]);
                }
        }
    };

    load_stage(0, 0); cp_commit();
    load_stage(1, 1); cp_commit();

    for (int t = 0; t < T; t++) {
        if (t < T - 1) cp_wait<1>(); else cp_wait<0>();
        __syncthreads();
        if (t + 2 < T) { load_stage(t + 2, (t + 2) % STAGES); cp_commit(); }
        compute_stage(t % STAGES);
    }

    // ---------------- epilogue ----------------
    const int groupID = lane >> 2, tIdx = lane & 3;
    #pragma unroll
    for (int fm = 0; fm < 2; fm++) {
        #pragma unroll
        for (int half = 0; half < 2; half++) {
            int row = bm + wm * 32 + fm * 16 + half * 8 + groupID;
            long long rbase = (long long)bz * cS + (long long)row * N;
            #pragma unroll
            for (int fn = 0; fn < 4; fn++) {
                int col = bn + wn * 32 + fn * 8 + tIdx * 2;
                float v0 = acc[fm][fn][half * 2 + 0];
                float v1 = acc[fm][fn][half * 2 + 1];
                if (bias) { v0 += __ldg(bias + col); v1 += __ldg(bias + col + 1); }
                if (RELU) { v0 = fmaxf(v0, 0.0f); v1 = fmaxf(v1, 0.0f); }
                if (HASRES) {
                    float2 rv = *(const float2*)(Res + rbase + col);
                    v0 += rv.x; v1 += rv.y;
                }
                if (F32OUT)
                    *(float2*)(Cf + rbase + col) = make_float2(v0, v1);
                if (HALFOUT)
                    *(uint32_t*)(Ch + rbase + col) =
                        pack2h(__float2half_rn(v0), __float2half_rn(v1));
                if (SPLITOUT) {
                    h16 h0, l0, h1, l1;
                    split1h(v0, h0, l0); split1h(v1, h1, l1);
                    *(uint32_t*)(Chi + rbase + col) = pack2h(h0, h1);
                    *(uint32_t*)(Clo + rbase + col) = pack2h(l0, l1);
                }
            }
        }
    }
}

// ---------------------------------------------------------------------------
// Elementwise quantize: fp32 -> fp16
// ---------------------------------------------------------------------------
__global__ __launch_bounds__(256) void quant_kernel(
    const float* __restrict__ src, h16* __restrict__ dst, int n4)
{
    int i = blockIdx.x * 256 + threadIdx.x;
    if (i >= n4) return;
    float4 v = ((const float4*)src)[i];
    ((uint2*)dst)[i] = make_uint2(
        pack2h(__float2half_rn(v.x), __float2half_rn(v.y)),
        pack2h(__float2half_rn(v.z), __float2half_rn(v.w)));
}

// ---------------------------------------------------------------------------
// Transpose-split: src [R,C] fp32 -> dst [C,R] (hi, lo) fp16.
// ---------------------------------------------------------------------------
__global__ __launch_bounds__(256) void transpose_split_kernel(
    const float* __restrict__ src, h16* __restrict__ hiT, h16* __restrict__ loT,
    int R, int C, long long sS, long long dS)
{
    __shared__ float tile[32][33];
    const float* S = src + (long long)blockIdx.z * sS;
    int c0 = blockIdx.x * 32, r0 = blockIdx.y * 32;
    int tx = threadIdx.x & 31, ty = threadIdx.x >> 5;   // 32 x 8
    #pragma unroll
    for (int i = 0; i < 32; i += 8)
        tile[ty + i][tx] = S[(long long)(r0 + ty + i) * C + c0 + tx];
    __syncthreads();
    #pragma unroll
    for (int i = 0; i < 32; i += 8) {
        float v = tile[tx][ty + i];
        h16 h, l; split1h(v, h, l);
        long long o = (long long)blockIdx.z * dS + (long long)(c0 + ty + i) * R + r0 + tx;
        hiT[o] = h; loT[o] = l;
    }
}

// Batched version for the four 1024x1024 weights: z picks the weight.
__global__ __launch_bounds__(256) void transpose_split4_kernel(
    const float* __restrict__ s0, const float* __restrict__ s1,
    const float* __restrict__ s2, const float* __restrict__ s3,
    h16* __restrict__ h0, h16* __restrict__ l0,
    h16* __restrict__ h1, h16* __restrict__ l1,
    h16* __restrict__ h2, h16* __restrict__ l2,
    h16* __restrict__ h3, h16* __restrict__ l3)
{
    __shared__ float tile[32][33];
    const int z = blockIdx.z;
    const float* S = (z == 0) ? s0 : (z == 1) ? s1 : (z == 2) ? s2 : s3;
    h16* H = (z == 0) ? h0 : (z == 1) ? h1 : (z == 2) ? h2 : h3;
    h16* L = (z == 0) ? l0 : (z == 1) ? l1 : (z == 2) ? l2 : l3;
    int c0 = blockIdx.x * 32, r0 = blockIdx.y * 32;
    int tx = threadIdx.x & 31, ty = threadIdx.x >> 5;
    #pragma unroll
    for (int i = 0; i < 32; i += 8)
        tile[ty + i][tx] = S[(long long)(r0 + ty + i) * D_MODEL + c0 + tx];
    __syncthreads();
    #pragma unroll
    for (int i = 0; i < 32; i += 8) {
        float v = tile[tx][ty + i];
        h16 h, l; split1h(v, h, l);
        long long o = (long long)(c0 + ty + i) * D_MODEL + r0 + tx;
        H[o] = h; L[o] = l;
    }
}

// ------------------------------- reductions --------------------------------
__device__ __forceinline__ float block_sum(float v) {
    __shared__ float sh[8];
    int lane = threadIdx.x & 31, w = threadIdx.x >> 5;
    #pragma unroll
    for (int o = 16; o > 0; o >>= 1) v += __shfl_xor_sync(0xffffffffu, v, o);
    if (lane == 0) sh[w] = v;
    __syncthreads();
    if (w == 0) {
        float t = (lane < 8) ? sh[lane] : 0.0f;
        #pragma unroll
        for (int o = 4; o > 0; o >>= 1) t += __shfl_xor_sync(0xffffffffu, t, o);
        if (lane == 0) sh[0] = t;
    }
    __syncthreads();
    float r = sh[0];
    __syncthreads();
    return r;
}
__device__ __forceinline__ float block_max(float v) {
    __shared__ float sh[8];
    int lane = threadIdx.x & 31, w = threadIdx.x >> 5;
    #pragma unroll
    for (int o = 16; o > 0; o >>= 1) v = fmaxf(v, __shfl_xor_sync(0xffffffffu, v, o));
    if (lane == 0) sh[w] = v;
    __syncthreads();
    if (w == 0) {
        float t = (lane < 8) ? sh[lane] : -3.4e38f;
        #pragma unroll
        for (int o = 4; o > 0; o >>= 1) t = fmaxf(t, __shfl_xor_sync(0xffffffffu, t, o));
        if (lane == 0) sh[0] = t;
    }
    __syncthreads();
    float r = sh[0];
    __syncthreads();
    return r;
}

// ---------------------------------------------------------------------------
// Softmax over SEQ=2048 with fused 1/scale; fp16 output.
// ---------------------------------------------------------------------------
__global__ __launch_bounds__(256) void softmax_kernel(
    const float* __restrict__ S, h16* __restrict__ P)
{
    const float inv_scale = 0.0883883476483184f;  // 1/sqrt(128)
    const float* row = S + (long long)blockIdx.x * SEQ;
    int tid = threadIdx.x;

    float4 a = ((const float4*)row)[tid];
    float4 b = ((const float4*)row)[tid + 256];
    a.x*=inv_scale; a.y*=inv_scale; a.z*=inv_scale; a.w*=inv_scale;
    b.x*=inv_scale; b.y*=inv_scale; b.z*=inv_scale; b.w*=inv_scale;

    float m = fmaxf(fmaxf(fmaxf(a.x,a.y), fmaxf(a.z,a.w)),
                    fmaxf(fmaxf(b.x,b.y), fmaxf(b.z,b.w)));
    m = block_max(m);
    a.x=expf(a.x-m); a.y=expf(a.y-m); a.z=expf(a.z-m); a.w=expf(a.w-m);
    b.x=expf(b.x-m); b.y=expf(b.y-m); b.z=expf(b.z-m); b.w=expf(b.w-m);
    float s = a.x+a.y+a.z+a.w + b.x+b.y+b.z+b.w;
    s = block_sum(s);
    float inv = 1.0f / s;
    a.x*=inv; a.y*=inv; a.z*=inv; a.w*=inv;
    b.x*=inv; b.y*=inv; b.z*=inv; b.w*=inv;

    long long base = (long long)blockIdx.x * SEQ;
    ((uint2*)(P + base))[tid] = make_uint2(
        pack2h(__float2half_rn(a.x), __float2half_rn(a.y)),
        pack2h(__float2half_rn(a.z), __float2half_rn(a.w)));
    ((uint2*)(P + base))[tid + 256] = make_uint2(
        pack2h(__float2half_rn(b.x), __float2half_rn(b.y)),
        pack2h(__float2half_rn(b.z), __float2half_rn(b.w)));
}

// ---------------------------------------------------------------------------
// LayerNorm D=1024; optional fp16 quantized emission.
// ---------------------------------------------------------------------------
template<bool EMITH>
__global__ __launch_bounds__(256) void layernorm_kernel(
    const float* __restrict__ X, const float* __restrict__ g,
    const float* __restrict__ b, float* __restrict__ Y, h16* __restrict__ Yh)
{
    const float* x = X + (long long)blockIdx.x * D_MODEL;
    int tid = threadIdx.x;
    float4 v = ((const float4*)x)[tid];
    float s = v.x + v.y + v.z + v.w;
    s = block_sum(s);
    float mean = s * (1.0f / D_MODEL);
    float dx=v.x-mean, dy=v.y-mean, dz=v.z-mean, dw=v.w-mean;
    float ss = dx*dx + dy*dy + dz*dz + dw*dw;
    ss = block_sum(ss);
    float rstd = rsqrtf(ss * (1.0f / D_MODEL) + 1e-5f);
    float4 gg = ((const float4*)g)[tid];
    float4 bb = ((const float4*)b)[tid];
    float4 o;
    o.x = dx*rstd*gg.x + bb.x;
    o.y = dy*rstd*gg.y + bb.y;
    o.z = dz*rstd*gg.z + bb.z;
    o.w = dw*rstd*gg.w + bb.w;
    long long base = (long long)blockIdx.x * D_MODEL;
    ((float4*)(Y + base))[tid] = o;
    if (EMITH) {
        ((uint2*)(Yh + base))[tid] = make_uint2(
            pack2h(__float2half_rn(o.x), __float2half_rn(o.y)),
            pack2h(__float2half_rn(o.z), __float2half_rn(o.w)));
    }
}

// ---------------------------------------------------------------------------
// Launch
// ---------------------------------------------------------------------------
extern "C" void kernel_launch(void* const* d_in, const int* in_sizes, int n_in,
                              void* d_out, int out_size)
{
    const float* x     = (const float*)d_in[0];
    const float* wq    = (const float*)d_in[1];
    const float* bq    = (const float*)d_in[2];
    const float* wk    = (const float*)d_in[3];
    const float* bk    = (const float*)d_in[4];
    const float* wv    = (const float*)d_in[5];
    const float* bv    = (const float*)d_in[6];
    const float* wo    = (const float*)d_in[7];
    const float* bo    = (const float*)d_in[8];
    const float* w1    = (const float*)d_in[9];
    const float* b1    = (const float*)d_in[10];
    const float* w2    = (const float*)d_in[11];
    const float* b2    = (const float*)d_in[12];
    const float* g1    = (const float*)d_in[13];
    const float* beta1 = (const float*)d_in[14];
    const float* g2    = (const float*)d_in[15];
    const float* beta2 = (const float*)d_in[16];
    float* out = (float*)d_out;

    #define SYM(p, s) void* p##_; cudaGetSymbolAddress(&p##_, s);
    SYM(x16, g_x16)
    SYM(wqh, g_wqT_h) SYM(wql, g_wqT_l)
    SYM(wkh, g_wkT_h) SYM(wkl, g_wkT_l)
    SYM(wvh, g_wvT_h) SYM(wvl, g_wvT_l)
    SYM(woh, g_woT_h) SYM(wol, g_woT_l)
    SYM(w1h, g_w1T_h) SYM(w1l, g_w1T_l)
    SYM(w2h, g_w2T_h) SYM(w2l, g_w2T_l)
    SYM(q16, g_q16)  SYM(kh, g_k_h)  SYM(kl, g_k_l)
    SYM(vv, g_v)     SYM(vth, g_vT_h) SYM(vtl, g_vT_l)
    SYM(sc, g_s)     SYM(p16, g_p16)
    SYM(c16, g_ctx16)
    SYM(x1, g_x1)    SYM(y1, g_y1)  SYM(y116, g_y116)
    SYM(hh, g_h16a)
    SYM(x2, g_x2)
    #undef SYM

    cudaFuncSetAttribute(gemm_nt<1,0,0,0,0>, cudaFuncAttributeMaxDynamicSharedMemorySize, SMEM_TOTAL);
    cudaFuncSetAttribute(gemm_nt<0,1,0,0,0>, cudaFuncAttributeMaxDynamicSharedMemorySize, SMEM_TOTAL);
    cudaFuncSetAttribute(gemm_nt<0,0,1,0,0>, cudaFuncAttributeMaxDynamicSharedMemorySize, SMEM_TOTAL);
    cudaFuncSetAttribute(gemm_nt<0,1,0,1,0>, cudaFuncAttributeMaxDynamicSharedMemorySize, SMEM_TOTAL);
    cudaFuncSetAttribute(gemm_nt<1,0,0,0,1>, cudaFuncAttributeMaxDynamicSharedMemorySize, SMEM_TOTAL);

    dim3 blk(256);

    // 0. quantize x -> fp16
    quant_kernel<<<M_TOT * D_MODEL / 4 / 256, blk>>>(x, (h16*)x16_, M_TOT * D_MODEL / 4);

    // 1. transpose-split the four DxD weights
    transpose_split4_kernel<<<dim3(D_MODEL/32, D_MODEL/32, 4), blk>>>(
        wq, wk, wv, wo,
        (h16*)wqh_, (h16*)wql_, (h16*)wkh_, (h16*)wkl_,
        (h16*)wvh_, (h16*)wvl_, (h16*)woh_, (h16*)wol_);

    // 2-4. q (fp16 out), k (split out), v (fp32 out)   [launch #2 = GEMM]
    {
        dim3 g(D_MODEL/BN, M_TOT/BM, 1);
        gemm_nt<0,1,0,0,0><<<g, blk, SMEM_TOTAL>>>(
            (h16*)x16_, (h16*)wqh_, (h16*)wql_, bq, nullptr,
            nullptr, (h16*)q16_, nullptr, nullptr,
            M_TOT, D_MODEL, D_MODEL, 0, 0, 0);
        gemm_nt<0,0,1,0,0><<<g, blk, SMEM_TOTAL>>>(
            (h16*)x16_, (h16*)wkh_, (h16*)wkl_, bk, nullptr,
            nullptr, nullptr, (h16*)kh_, (h16*)kl_,
            M_TOT, D_MODEL, D_MODEL, 0, 0, 0);
        gemm_nt<1,0,0,0,0><<<g, blk, SMEM_TOTAL>>>(
            (h16*)x16_, (h16*)wvh_, (h16*)wvl_, bv, nullptr,
            (float*)vv_, nullptr, nullptr, nullptr,
            M_TOT, D_MODEL, D_MODEL, 0, 0, 0);
    }

    // 5-6. w1, w2 transposes
    transpose_split_kernel<<<dim3(FF_DIM/32, D_MODEL/32, 1), blk>>>(w1, (h16*)w1h_, (h16*)w1l_, D_MODEL, FF_DIM, 0, 0);
    transpose_split_kernel<<<dim3(D_MODEL/32, FF_DIM/32, 1), blk>>>(w2, (h16*)w2h_, (h16*)w2l_, FF_DIM, D_MODEL, 0, 0);

    // 7. vT per batch: [2048,1024] -> [1024,2048] hi/lo
    transpose_split_kernel<<<dim3(D_MODEL/32, SEQ/32, BATCH), blk>>>((float*)vv_,
        (h16*)vth_, (h16*)vtl_, SEQ, D_MODEL, (long long)SEQ*D_MODEL, (long long)SEQ*D_MODEL);

    // 8. scores = q @ k^T (fp32 out)
    gemm_nt<1,0,0,0,0><<<dim3(SEQ/BN, SEQ/BM, BATCH), blk, SMEM_TOTAL>>>(
        (h16*)q16_, (h16*)kh_, (h16*)kl_, nullptr, nullptr,
        (float*)sc_, nullptr, nullptr, nullptr,
        SEQ, SEQ, D_MODEL,
        (long long)SEQ*D_MODEL, (long long)SEQ*D_MODEL, (long long)SEQ*SEQ);

    // 9. softmax -> fp16 P
    softmax_kernel<<<BATCH*SEQ, blk>>>((float*)sc_, (h16*)p16_);

    // 10. ctx = P @ vT^T (fp16 out)
    gemm_nt<0,1,0,0,0><<<dim3(D_MODEL/BN, SEQ/BM, BATCH), blk, SMEM_TOTAL>>>(
        (h16*)p16_, (h16*)vth_, (h16*)vtl_, nullptr, nullptr,
        nullptr, (h16*)c16_, nullptr, nullptr,
        SEQ, D_MODEL, SEQ,
        (long long)SEQ*SEQ, (long long)SEQ*D_MODEL, (long long)SEQ*D_MODEL);

    // 11. x1 = x + ctx @ wo^T + bo
    gemm_nt<1,0,0,0,1><<<dim3(D_MODEL/BN, M_TOT/BM, 1), blk, SMEM_TOTAL>>>(
        (h16*)c16_, (h16*)woh_, (h16*)wol_, bo, x,
        (float*)x1_, nullptr, nullptr, nullptr,
        M_TOT, D_MODEL, D_MODEL, 0, 0, 0);

    // 12. y1 = LN1(x1), emit fp16
    layernorm_kernel<true><<<M_TOT, blk>>>((float*)x1_, g1, beta1, (float*)y1_, (h16*)y116_);

    // 13. h = relu(y1 @ w1^T + b1) (fp16 out)
    gemm_nt<0,1,0,1,0><<<dim3(FF_DIM/BN, M_TOT/BM, 1), blk, SMEM_TOTAL>>>(
        (h16*)y116_, (h16*)w1h_, (h16*)w1l_, b1, nullptr,
        nullptr, (h16*)hh_, nullptr, nullptr,
        M_TOT, FF_DIM, D_MODEL, 0, 0, 0);

    // 14. x2 = y1 + h @ w2^T + b2
    gemm_nt<1,0,0,0,1><<<dim3(D_MODEL/BN, M_TOT/BM, 1), blk, SMEM_TOTAL>>>(
        (h16*)hh_, (h16*)w2h_, (h16*)w2l_, b2, (float*)y1_,
        (float*)x2_, nullptr, nullptr, nullptr,
        M_TOT, D_MODEL, FF_DIM, 0, 0, 0);

    // 15. out = LN2(x2)
    layernorm_kernel<false><<<M_TOT, blk>>>((float*)x2_, g2, beta2, out, nullptr);
}

// round 9
// speedup vs baseline: 4.5040x; 1.0157x over previous
#include <cuda_runtime.h>
#include <cuda_fp16.h>
#include <math.h>
#include <stdint.h>

// ---------------------------------------------------------------------------
// SmallTransformerBlock via mma.sync fp16 asymmetric-split GEMMs (sm_103 PTX).
// C = A16 @ (Bh + Bl)^T : A fp16, B split hi+lo fp16, 2 MMA passes.
// R9: 2-stage pipeline (64KB smem), 3 CTAs/SM, fully hoisted ldsm/cp.async
// address math (6 ldsm bases + XOR ks-term; 3 global pointers + row stride).
// ---------------------------------------------------------------------------

#define D_MODEL 1024
#define FF_DIM  4096
#define BATCH   4
#define SEQ     2048
#define M_TOT   (BATCH * SEQ)          // 8192

#define BM 128
#define BN 64
#define BK 64
#define STAGES 2
#define ABUF_BYTES (128 * 128)                 // A: 128 rows x 128B (64 fp16)
#define BBUF_BYTES (64 * 128)                  // Bh: 64 rows x 128B; Bl same
#define STAGE_BYTES (ABUF_BYTES + 2 * BBUF_BYTES)   // 32768
#define SMEM_TOTAL  (STAGES * STAGE_BYTES)          // 65536

typedef __half h16;

// -------------------------- scratch (device globals) -----------------------
__device__ h16   g_x16  [M_TOT * D_MODEL];
__device__ h16   g_wqT_h[D_MODEL * D_MODEL];
__device__ h16   g_wqT_l[D_MODEL * D_MODEL];
__device__ h16   g_wkT_h[D_MODEL * D_MODEL];
__device__ h16   g_wkT_l[D_MODEL * D_MODEL];
__device__ h16   g_wvT_h[D_MODEL * D_MODEL];
__device__ h16   g_wvT_l[D_MODEL * D_MODEL];
__device__ h16   g_woT_h[D_MODEL * D_MODEL];
__device__ h16   g_woT_l[D_MODEL * D_MODEL];
__device__ h16   g_w1T_h[FF_DIM * D_MODEL];
__device__ h16   g_w1T_l[FF_DIM * D_MODEL];
__device__ h16   g_w2T_h[D_MODEL * FF_DIM];
__device__ h16   g_w2T_l[D_MODEL * FF_DIM];
__device__ h16   g_q16  [M_TOT * D_MODEL];
__device__ h16   g_k_h  [M_TOT * D_MODEL];
__device__ h16   g_k_l  [M_TOT * D_MODEL];
__device__ float g_v    [M_TOT * D_MODEL];
__device__ h16   g_vT_h [M_TOT * D_MODEL];     // [B][D,T]
__device__ h16   g_vT_l [M_TOT * D_MODEL];
__device__ float g_s    [BATCH * SEQ * SEQ];
__device__ h16   g_p16  [BATCH * SEQ * SEQ];
__device__ h16   g_ctx16[M_TOT * D_MODEL];
__device__ float g_x1   [M_TOT * D_MODEL];
__device__ float g_y1   [M_TOT * D_MODEL];
__device__ h16   g_y116 [M_TOT * D_MODEL];
__device__ h16   g_h16a [M_TOT * FF_DIM];
__device__ float g_x2   [M_TOT * D_MODEL];

// ------------------------------- PTX helpers -------------------------------
__device__ __forceinline__ uint32_t smem_u32(const void* p) {
    uint32_t a;
    asm("{ .reg .u64 t; cvta.to.shared.u64 t, %1; cvt.u32.u64 %0, t; }"
        : "=r"(a) : "l"(p));
    return a;
}
__device__ __forceinline__ void cp16(uint32_t dst, const void* src) {
    asm volatile("cp.async.cg.shared.global [%0], [%1], 16;\n" :: "r"(dst), "l"(src));
}
__device__ __forceinline__ void cp_commit() {
    asm volatile("cp.async.commit_group;\n" ::: "memory");
}
template<int N> __device__ __forceinline__ void cp_wait() {
    asm volatile("cp.async.wait_group %0;\n" :: "n"(N) : "memory");
}
__device__ __forceinline__ void ldsm4(uint32_t& r0, uint32_t& r1, uint32_t& r2,
                                      uint32_t& r3, uint32_t addr) {
    asm volatile("ldmatrix.sync.aligned.m8n8.x4.shared.b16 {%0,%1,%2,%3}, [%4];\n"
                 : "=r"(r0), "=r"(r1), "=r"(r2), "=r"(r3) : "r"(addr));
}
__device__ __forceinline__ void mma16816(float* d, const uint32_t* a, const uint32_t* b) {
    asm volatile(
        "mma.sync.aligned.m16n8k16.row.col.f32.f16.f16.f32 "
        "{%0,%1,%2,%3}, {%4,%5,%6,%7}, {%8,%9}, {%0,%1,%2,%3};\n"
        : "+f"(d[0]), "+f"(d[1]), "+f"(d[2]), "+f"(d[3])
        : "r"(a[0]), "r"(a[1]), "r"(a[2]), "r"(a[3]), "r"(b[0]), "r"(b[1]));
}
__device__ __forceinline__ void split1h(float v, h16& h, h16& l) {
    h = __float2half_rn(v);
    l = __float2half_rn(v - __half2float(h));
}
__device__ __forceinline__ uint32_t pack2h(h16 a, h16 b) {
    return ((uint32_t)__half_as_ushort(b) << 16) | __half_as_ushort(a);
}

// ---------------------------------------------------------------------------
// GEMM NT fp16 2-pass: C[M,N] = A16 @ (Bh+Bl)^T (+bias)(relu)(+res)
// 128x64x64 tile, 8 warps (warp tile 32x32), 2-stage cp.async, 3 CTAs/SM.
// ---------------------------------------------------------------------------
template<bool F32OUT, bool HALFOUT, bool SPLITOUT, bool RELU, bool HASRES>
__global__ __launch_bounds__(256, 3) void gemm_nt(
    const h16* __restrict__ A16,
    const h16* __restrict__ Bhi, const h16* __restrict__ Blo,
    const float* __restrict__ bias, const float* __restrict__ Res,
    float* __restrict__ Cf, h16* __restrict__ Ch,
    h16* __restrict__ Chi, h16* __restrict__ Clo,
    int M, int N, int K, long long aS, long long bS, long long cS)
{
    extern __shared__ char smraw[];
    const uint32_t smb = smem_u32(smraw);
    const int tid  = threadIdx.x;
    const int wid  = tid >> 5;
    const int lane = tid & 31;
    const int wm = wid & 3;            // m offset wm*32
    const int wn = wid >> 2;           // n offset wn*32
    const int quad = lane >> 3, lrow = lane & 7;
    const int bz = blockIdx.z;
    const int bm = blockIdx.y * BM;
    const int bn = blockIdx.x * BN;

    // ---- hoisted global load pointers (3 ptrs + row stride) ----
    const int trow = tid >> 3;                 // 0..31
    const int lc   = tid & 7;                  // 16B chunk 0..7
    const int lk   = lc * 8;                   // k element offset
    const long long rowStep = 32LL * K;        // 32 rows, in elements
    const h16* pA  = A16 + (long long)bz * aS + (long long)(bm + trow) * K + lk;
    const h16* pBh = Bhi + (long long)bz * bS + (long long)(bn + trow) * K + lk;
    const h16* pBl = Blo + (long long)bz * bS + (long long)(bn + trow) * K + lk;
    // shared dst offset (same for A row trow and B row trow)
    const uint32_t d0 = (uint32_t)(trow * 128 + ((lc ^ (trow & 7)) * 16));

    // ---- hoisted ldsm base addresses (swizzle decomposed) ----
    // addr = stage + base[target] + (((2ks) ^ (lrow&6)) << 4)
    const uint32_t bit4  = (uint32_t)(((quad >> 1) ^ (lrow & 1)) << 4);
    const uint32_t lrow6 = (uint32_t)(lrow & 6);
    uint32_t baseA[2], baseBh[2], baseBl[2];
    #pragma unroll
    for (int fm = 0; fm < 2; fm++)
        baseA[fm] = (uint32_t)((wm * 32 + fm * 16 + (quad & 1) * 8 + lrow) * 128) + bit4;
    #pragma unroll
    for (int f2 = 0; f2 < 2; f2++) {
        uint32_t r = (uint32_t)((wn * 32 + f2 * 16 + (quad & 1) * 8 + lrow) * 128);
        baseBh[f2] = ABUF_BYTES + r + bit4;
        baseBl[f2] = ABUF_BYTES + BBUF_BYTES + r + bit4;
    }

    float acc[2][4][4];
    #pragma unroll
    for (int i = 0; i < 2; i++)
        #pragma unroll
        for (int j = 0; j < 4; j++)
            #pragma unroll
            for (int c = 0; c < 4; c++) acc[i][j][c] = 0.0f;

    const int T = K / BK;

    auto load_stage = [&](int kt, int s) {
        const uint32_t stb = smb + (uint32_t)s * STAGE_BYTES;
        const int k0 = kt * BK;
        cp16(stb + d0,          pA + k0);
        cp16(stb + d0 + 4096,   pA + rowStep + k0);
        cp16(stb + d0 + 8192,   pA + 2 * rowStep + k0);
        cp16(stb + d0 + 12288,  pA + 3 * rowStep + k0);
        cp16(stb + ABUF_BYTES + d0,          pBh + k0);
        cp16(stb + ABUF_BYTES + d0 + 4096,   pBh + rowStep + k0);
        cp16(stb + ABUF_BYTES + BBUF_BYTES + d0,        pBl + k0);
        cp16(stb + ABUF_BYTES + BBUF_BYTES + d0 + 4096, pBl + rowStep + k0);
    };

    auto compute_stage = [&](int s) {
        const uint32_t stb = smb + (uint32_t)s * STAGE_BYTES;
        #pragma unroll
        for (int ks = 0; ks < 4; ks++) {
            const uint32_t kk = ((uint32_t)(ks * 2) ^ lrow6) << 4;
            uint32_t ah[2][4];
            #pragma unroll
            for (int fm = 0; fm < 2; fm++)
                ldsm4(ah[fm][0], ah[fm][1], ah[fm][2], ah[fm][3],
                      stb + baseA[fm] + kk);
            uint32_t bh[4][2], bl[4][2];
            #pragma unroll
            for (int f2 = 0; f2 < 2; f2++) {
                uint32_t t0, t1, t2, t3;
                ldsm4(t0, t1, t2, t3, stb + baseBh[f2] + kk);
                bh[2*f2][0] = t0; bh[2*f2][1] = t2;
                bh[2*f2+1][0] = t1; bh[2*f2+1][1] = t3;
                ldsm4(t0, t1, t2, t3, stb + baseBl[f2] + kk);
                bl[2*f2][0] = t0; bl[2*f2][1] = t2;
                bl[2*f2+1][0] = t1; bl[2*f2+1][1] = t3;
            }
            #pragma unroll
            for (int fm = 0; fm < 2; fm++)
                #pragma unroll
                for (int fn = 0; fn < 4; fn++) {
                    float* d = acc[fm][fn];
                    mma16816(d, ah[fm], bh[fn]);
                    mma16816(d, ah[fm], bl[fn]);
                }
        }
    };

    load_stage(0, 0); cp_commit();
    load_stage(1, 1); cp_commit();

    for (int t = 0; t < T; t++) {
        if (t < T - 1) cp_wait<1>(); else cp_wait<0>();
        __syncthreads();
        compute_stage(t & 1);
        if (t < T - 2) {
            __syncthreads();
            load_stage(t + 2, t & 1); cp_commit();
        }
    }

    // ---------------- epilogue ----------------
    const int groupID = lane >> 2, tIdx = lane & 3;
    #pragma unroll
    for (int fm = 0; fm < 2; fm++) {
        #pragma unroll
        for (int half = 0; half < 2; half++) {
            int row = bm + wm * 32 + fm * 16 + half * 8 + groupID;
            long long rbase = (long long)bz * cS + (long long)row * N;
            #pragma unroll
            for (int fn = 0; fn < 4; fn++) {
                int col = bn + wn * 32 + fn * 8 + tIdx * 2;
                float v0 = acc[fm][fn][half * 2 + 0];
                float v1 = acc[fm][fn][half * 2 + 1];
                if (bias) { v0 += __ldg(bias + col); v1 += __ldg(bias + col + 1); }
                if (RELU) { v0 = fmaxf(v0, 0.0f); v1 = fmaxf(v1, 0.0f); }
                if (HASRES) {
                    float2 rv = *(const float2*)(Res + rbase + col);
                    v0 += rv.x; v1 += rv.y;
                }
                if (F32OUT)
                    *(float2*)(Cf + rbase + col) = make_float2(v0, v1);
                if (HALFOUT)
                    *(uint32_t*)(Ch + rbase + col) =
                        pack2h(__float2half_rn(v0), __float2half_rn(v1));
                if (SPLITOUT) {
                    h16 h0, l0, h1, l1;
                    split1h(v0, h0, l0); split1h(v1, h1, l1);
                    *(uint32_t*)(Chi + rbase + col) = pack2h(h0, h1);
                    *(uint32_t*)(Clo + rbase + col) = pack2h(l0, l1);
                }
            }
        }
    }
}

// ---------------------------------------------------------------------------
// Elementwise quantize: fp32 -> fp16
// ---------------------------------------------------------------------------
__global__ __launch_bounds__(256) void quant_kernel(
    const float* __restrict__ src, h16* __restrict__ dst, int n4)
{
    int i = blockIdx.x * 256 + threadIdx.x;
    if (i >= n4) return;
    float4 v = ((const float4*)src)[i];
    ((uint2*)dst)[i] = make_uint2(
        pack2h(__float2half_rn(v.x), __float2half_rn(v.y)),
        pack2h(__float2half_rn(v.z), __float2half_rn(v.w)));
}

// ---------------------------------------------------------------------------
// Transpose-split: src [R,C] fp32 -> dst [C,R] (hi, lo) fp16.
// ---------------------------------------------------------------------------
__global__ __launch_bounds__(256) void transpose_split_kernel(
    const float* __restrict__ src, h16* __restrict__ hiT, h16* __restrict__ loT,
    int R, int C, long long sS, long long dS)
{
    __shared__ float tile[32][33];
    const float* S = src + (long long)blockIdx.z * sS;
    int c0 = blockIdx.x * 32, r0 = blockIdx.y * 32;
    int tx = threadIdx.x & 31, ty = threadIdx.x >> 5;   // 32 x 8
    #pragma unroll
    for (int i = 0; i < 32; i += 8)
        tile[ty + i][tx] = S[(long long)(r0 + ty + i) * C + c0 + tx];
    __syncthreads();
    #pragma unroll
    for (int i = 0; i < 32; i += 8) {
        float v = tile[tx][ty + i];
        h16 h, l; split1h(v, h, l);
        long long o = (long long)blockIdx.z * dS + (long long)(c0 + ty + i) * R + r0 + tx;
        hiT[o] = h; loT[o] = l;
    }
}

// Batched version for the four 1024x1024 weights: z picks the weight.
__global__ __launch_bounds__(256) void transpose_split4_kernel(
    const float* __restrict__ s0, const float* __restrict__ s1,
    const float* __restrict__ s2, const float* __restrict__ s3,
    h16* __restrict__ h0, h16* __restrict__ l0,
    h16* __restrict__ h1, h16* __restrict__ l1,
    h16* __restrict__ h2, h16* __restrict__ l2,
    h16* __restrict__ h3, h16* __restrict__ l3)
{
    __shared__ float tile[32][33];
    const int z = blockIdx.z;
    const float* S = (z == 0) ? s0 : (z == 1) ? s1 : (z == 2) ? s2 : s3;
    h16* H = (z == 0) ? h0 : (z == 1) ? h1 : (z == 2) ? h2 : h3;
    h16* L = (z == 0) ? l0 : (z == 1) ? l1 : (z == 2) ? l2 : l3;
    int c0 = blockIdx.x * 32, r0 = blockIdx.y * 32;
    int tx = threadIdx.x & 31, ty = threadIdx.x >> 5;
    #pragma unroll
    for (int i = 0; i < 32; i += 8)
        tile[ty + i][tx] = S[(long long)(r0 + ty + i) * D_MODEL + c0 + tx];
    __syncthreads();
    #pragma unroll
    for (int i = 0; i < 32; i += 8) {
        float v = tile[tx][ty + i];
        h16 h, l; split1h(v, h, l);
        long long o = (long long)(c0 + ty + i) * D_MODEL + r0 + tx;
        H[o] = h; L[o] = l;
    }
}

// ------------------------------- reductions --------------------------------
__device__ __forceinline__ float block_sum(float v) {
    __shared__ float sh[8];
    int lane = threadIdx.x & 31, w = threadIdx.x >> 5;
    #pragma unroll
    for (int o = 16; o > 0; o >>= 1) v += __shfl_xor_sync(0xffffffffu, v, o);
    if (lane == 0) sh[w] = v;
    __syncthreads();
    if (w == 0) {
        float t = (lane < 8) ? sh[lane] : 0.0f;
        #pragma unroll
        for (int o = 4; o > 0; o >>= 1) t += __shfl_xor_sync(0xffffffffu, t, o);
        if (lane == 0) sh[0] = t;
    }
    __syncthreads();
    float r = sh[0];
    __syncthreads();
    return r;
}
__device__ __forceinline__ float block_max(float v) {
    __shared__ float sh[8];
    int lane = threadIdx.x & 31, w = threadIdx.x >> 5;
    #pragma unroll
    for (int o = 16; o > 0; o >>= 1) v = fmaxf(v, __shfl_xor_sync(0xffffffffu, v, o));
    if (lane == 0) sh[w] = v;
    __syncthreads();
    if (w == 0) {
        float t = (lane < 8) ? sh[lane] : -3.4e38f;
        #pragma unroll
        for (int o = 4; o > 0; o >>= 1) t = fmaxf(t, __shfl_xor_sync(0xffffffffu, t, o));
        if (lane == 0) sh[0] = t;
    }
    __syncthreads();
    float r = sh[0];
    __syncthreads();
    return r;
}

// ---------------------------------------------------------------------------
// Softmax over SEQ=2048 with fused 1/scale; fp16 output.
// ---------------------------------------------------------------------------
__global__ __launch_bounds__(256) void softmax_kernel(
    const float* __restrict__ S, h16* __restrict__ P)
{
    const float inv_scale = 0.0883883476483184f;  // 1/sqrt(128)
    const float* row = S + (long long)blockIdx.x * SEQ;
    int tid = threadIdx.x;

    float4 a = ((const float4*)row)[tid];
    float4 b = ((const float4*)row)[tid + 256];
    a.x*=inv_scale; a.y*=inv_scale; a.z*=inv_scale; a.w*=inv_scale;
    b.x*=inv_scale; b.y*=inv_scale; b.z*=inv_scale; b.w*=inv_scale;

    float m = fmaxf(fmaxf(fmaxf(a.x,a.y), fmaxf(a.z,a.w)),
                    fmaxf(fmaxf(b.x,b.y), fmaxf(b.z,b.w)));
    m = block_max(m);
    a.x=expf(a.x-m); a.y=expf(a.y-m); a.z=expf(a.z-m); a.w=expf(a.w-m);
    b.x=expf(b.x-m); b.y=expf(b.y-m); b.z=expf(b.z-m); b.w=expf(b.w-m);
    float s = a.x+a.y+a.z+a.w + b.x+b.y+b.z+b.w;
    s = block_sum(s);
    float inv = 1.0f / s;
    a.x*=inv; a.y*=inv; a.z*=inv; a.w*=inv;
    b.x*=inv; b.y*=inv; b.z*=inv; b.w*=inv;

    long long base = (long long)blockIdx.x * SEQ;
    ((uint2*)(P + base))[tid] = make_uint2(
        pack2h(__float2half_rn(a.x), __float2half_rn(a.y)),
        pack2h(__float2half_rn(a.z), __float2half_rn(a.w)));
    ((uint2*)(P + base))[tid + 256] = make_uint2(
        pack2h(__float2half_rn(b.x), __float2half_rn(b.y)),
        pack2h(__float2half_rn(b.z), __float2half_rn(b.w)));
}

// ---------------------------------------------------------------------------
// LayerNorm D=1024; optional fp16 quantized emission.
// ---------------------------------------------------------------------------
template<bool EMITH>
__global__ __launch_bounds__(256) void layernorm_kernel(
    const float* __restrict__ X, const float* __restrict__ g,
    const float* __restrict__ b, float* __restrict__ Y, h16* __restrict__ Yh)
{
    const float* x = X + (long long)blockIdx.x * D_MODEL;
    int tid = threadIdx.x;
    float4 v = ((const float4*)x)[tid];
    float s = v.x + v.y + v.z + v.w;
    s = block_sum(s);
    float mean = s * (1.0f / D_MODEL);
    float dx=v.x-mean, dy=v.y-mean, dz=v.z-mean, dw=v.w-mean;
    float ss = dx*dx + dy*dy + dz*dz + dw*dw;
    ss = block_sum(ss);
    float rstd = rsqrtf(ss * (1.0f / D_MODEL) + 1e-5f);
    float4 gg = ((const float4*)g)[tid];
    float4 bb = ((const float4*)b)[tid];
    float4 o;
    o.x = dx*rstd*gg.x + bb.x;
    o.y = dy*rstd*gg.y + bb.y;
    o.z = dz*rstd*gg.z + bb.z;
    o.w = dw*rstd*gg.w + bb.w;
    long long base = (long long)blockIdx.x * D_MODEL;
    ((float4*)(Y + base))[tid] = o;
    if (EMITH) {
        ((uint2*)(Yh + base))[tid] = make_uint2(
            pack2h(__float2half_rn(o.x), __float2half_rn(o.y)),
            pack2h(__float2half_rn(o.z), __float2half_rn(o.w)));
    }
}

// ---------------------------------------------------------------------------
// Launch
// ---------------------------------------------------------------------------
extern "C" void kernel_launch(void* const* d_in, const int* in_sizes, int n_in,
                              void* d_out, int out_size)
{
    const float* x     = (const float*)d_in[0];
    const float* wq    = (const float*)d_in[1];
    const float* bq    = (const float*)d_in[2];
    const float* wk    = (const float*)d_in[3];
    const float* bk    = (const float*)d_in[4];
    const float* wv    = (const float*)d_in[5];
    const float* bv    = (const float*)d_in[6];
    const float* wo    = (const float*)d_in[7];
    const float* bo    = (const float*)d_in[8];
    const float* w1    = (const float*)d_in[9];
    const float* b1    = (const float*)d_in[10];
    const float* w2    = (const float*)d_in[11];
    const float* b2    = (const float*)d_in[12];
    const float* g1    = (const float*)d_in[13];
    const float* beta1 = (const float*)d_in[14];
    const float* g2    = (const float*)d_in[15];
    const float* beta2 = (const float*)d_in[16];
    float* out = (float*)d_out;

    #define SYM(p, s) void* p##_; cudaGetSymbolAddress(&p##_, s);
    SYM(x16, g_x16)
    SYM(wqh, g_wqT_h) SYM(wql, g_wqT_l)
    SYM(wkh, g_wkT_h) SYM(wkl, g_wkT_l)
    SYM(wvh, g_wvT_h) SYM(wvl, g_wvT_l)
    SYM(woh, g_woT_h) SYM(wol, g_woT_l)
    SYM(w1h, g_w1T_h) SYM(w1l, g_w1T_l)
    SYM(w2h, g_w2T_h) SYM(w2l, g_w2T_l)
    SYM(q16, g_q16)  SYM(kh, g_k_h)  SYM(kl, g_k_l)
    SYM(vv, g_v)     SYM(vth, g_vT_h) SYM(vtl, g_vT_l)
    SYM(sc, g_s)     SYM(p16, g_p16)
    SYM(c16, g_ctx16)
    SYM(x1, g_x1)    SYM(y1, g_y1)  SYM(y116, g_y116)
    SYM(hh, g_h16a)
    SYM(x2, g_x2)
    #undef SYM

    cudaFuncSetAttribute(gemm_nt<1,0,0,0,0>, cudaFuncAttributeMaxDynamicSharedMemorySize, SMEM_TOTAL);
    cudaFuncSetAttribute(gemm_nt<0,1,0,0,0>, cudaFuncAttributeMaxDynamicSharedMemorySize, SMEM_TOTAL);
    cudaFuncSetAttribute(gemm_nt<0,0,1,0,0>, cudaFuncAttributeMaxDynamicSharedMemorySize, SMEM_TOTAL);
    cudaFuncSetAttribute(gemm_nt<0,1,0,1,0>, cudaFuncAttributeMaxDynamicSharedMemorySize, SMEM_TOTAL);
    cudaFuncSetAttribute(gemm_nt<1,0,0,0,1>, cudaFuncAttributeMaxDynamicSharedMemorySize, SMEM_TOTAL);

    dim3 blk(256);

    // 0. quantize x -> fp16
    quant_kernel<<<M_TOT * D_MODEL / 4 / 256, blk>>>(x, (h16*)x16_, M_TOT * D_MODEL / 4);

    // 1. transpose-split the four DxD weights
    transpose_split4_kernel<<<dim3(D_MODEL/32, D_MODEL/32, 4), blk>>>(
        wq, wk, wv, wo,
        (h16*)wqh_, (h16*)wql_, (h16*)wkh_, (h16*)wkl_,
        (h16*)wvh_, (h16*)wvl_, (h16*)woh_, (h16*)wol_);

    // 2-4. q (fp16 out), k (split out), v (fp32 out)   [launch #2 = GEMM]
    {
        dim3 g(D_MODEL/BN, M_TOT/BM, 1);
        gemm_nt<0,1,0,0,0><<<g, blk, SMEM_TOTAL>>>(
            (h16*)x16_, (h16*)wqh_, (h16*)wql_, bq, nullptr,
            nullptr, (h16*)q16_, nullptr, nullptr,
            M_TOT, D_MODEL, D_MODEL, 0, 0, 0);
        gemm_nt<0,0,1,0,0><<<g, blk, SMEM_TOTAL>>>(
            (h16*)x16_, (h16*)wkh_, (h16*)wkl_, bk, nullptr,
            nullptr, nullptr, (h16*)kh_, (h16*)kl_,
            M_TOT, D_MODEL, D_MODEL, 0, 0, 0);
        gemm_nt<1,0,0,0,0><<<g, blk, SMEM_TOTAL>>>(
            (h16*)x16_, (h16*)wvh_, (h16*)wvl_, bv, nullptr,
            (float*)vv_, nullptr, nullptr, nullptr,
            M_TOT, D_MODEL, D_MODEL, 0, 0, 0);
    }

    // 5-6. w1, w2 transposes
    transpose_split_kernel<<<dim3(FF_DIM/32, D_MODEL/32, 1), blk>>>(w1, (h16*)w1h_, (h16*)w1l_, D_MODEL, FF_DIM, 0, 0);
    transpose_split_kernel<<<dim3(D_MODEL/32, FF_DIM/32, 1), blk>>>(w2, (h16*)w2h_, (h16*)w2l_, FF_DIM, D_MODEL, 0, 0);

    // 7. vT per batch: [2048,1024] -> [1024,2048] hi/lo
    transpose_split_kernel<<<dim3(D_MODEL/32, SEQ/32, BATCH), blk>>>((float*)vv_,
        (h16*)vth_, (h16*)vtl_, SEQ, D_MODEL, (long long)SEQ*D_MODEL, (long long)SEQ*D_MODEL);

    // 8. scores = q @ k^T (fp32 out)
    gemm_nt<1,0,0,0,0><<<dim3(SEQ/BN, SEQ/BM, BATCH), blk, SMEM_TOTAL>>>(
        (h16*)q16_, (h16*)kh_, (h16*)kl_, nullptr, nullptr,
        (float*)sc_, nullptr, nullptr, nullptr,
        SEQ, SEQ, D_MODEL,
        (long long)SEQ*D_MODEL, (long long)SEQ*D_MODEL, (long long)SEQ*SEQ);

    // 9. softmax -> fp16 P
    softmax_kernel<<<BATCH*SEQ, blk>>>((float*)sc_, (h16*)p16_);

    // 10. ctx = P @ vT^T (fp16 out)
    gemm_nt<0,1,0,0,0><<<dim3(D_MODEL/BN, SEQ/BM, BATCH), blk, SMEM_TOTAL>>>(
        (h16*)p16_, (h16*)vth_, (h16*)vtl_, nullptr, nullptr,
        nullptr, (h16*)c16_, nullptr, nullptr,
        SEQ, D_MODEL, SEQ,
        (long long)SEQ*SEQ, (long long)SEQ*D_MODEL, (long long)SEQ*D_MODEL);

    // 11. x1 = x + ctx @ wo^T + bo
    gemm_nt<1,0,0,0,1><<<dim3(D_MODEL/BN, M_TOT/BM, 1), blk, SMEM_TOTAL>>>(
        (h16*)c16_, (h16*)woh_, (h16*)wol_, bo, x,
        (float*)x1_, nullptr, nullptr, nullptr,
        M_TOT, D_MODEL, D_MODEL, 0, 0, 0);

    // 12. y1 = LN1(x1), emit fp16
    layernorm_kernel<true><<<M_TOT, blk>>>((float*)x1_, g1, beta1, (float*)y1_, (h16*)y116_);

    // 13. h = relu(y1 @ w1^T + b1) (fp16 out)
    gemm_nt<0,1,0,1,0><<<dim3(FF_DIM/BN, M_TOT/BM, 1), blk, SMEM_TOTAL>>>(
        (h16*)y116_, (h16*)w1h_, (h16*)w1l_, b1, nullptr,
        nullptr, (h16*)hh_, nullptr, nullptr,
        M_TOT, FF_DIM, D_MODEL, 0, 0, 0);

    // 14. x2 = y1 + h @ w2^T + b2
    gemm_nt<1,0,0,0,1><<<dim3(D_MODEL/BN, M_TOT/BM, 1), blk, SMEM_TOTAL>>>(
        (h16*)hh_, (h16*)w2h_, (h16*)w2l_, b2, (float*)y1_,
        (float*)x2_, nullptr, nullptr, nullptr,
        M_TOT, D_MODEL, FF_DIM, 0, 0, 0);

    // 15. out = LN2(x2)
    layernorm_kernel<false><<<M_TOT, blk>>>((float*)x2_, g2, beta2, out, nullptr);
}